// round 3
// baseline (speedup 1.0000x reference)
#include <cuda_runtime.h>
#include <math.h>

#define EPSV 1e-5f
#define ALPHAV 100.0f

// ------------------------- scratch (device globals) -------------------------
__device__ __align__(16) float g_fa [2*64*4096];
__device__ __align__(16) float g_fb [2*64*4096];
__device__ __align__(16) float g_fan[2*64*4096];
__device__ __align__(16) float g_fbn[2*64*4096];
__device__ __align__(16) float g_mA[128], g_vA[128], g_mB[128], g_vB[128];
__device__ __align__(16) float g_cmA[128], g_cmB[128];
__device__ __align__(16) float g_fc1[2*3*128*128];
__device__ __align__(16) float g_fc2[2*3*64*64];
__device__ __align__(16) float g_fcw[2*3*64*64];
__device__ __align__(16) float g_up [2*3*256*256];
__device__ __align__(16) float g_cv [2*3*256*256];
__device__ __align__(16) float g_ms[16], g_vs[16];
__device__ __align__(16) float g_colmax[2*4096];
__device__ __align__(16) float g_srecip[2*4096];
__device__ __align__(16) float g_spart[2*16*4096];
__device__ __align__(16) float g_apart[2*16*3*4096];

// ------------------------- helpers -------------------------
__device__ __forceinline__ void atomicMaxF(float* addr, float val) {
    int* ia = (int*)addr;
    int old = *ia;
    while (__int_as_float(old) < val) {
        int assumed = old;
        old = atomicCAS(ia, assumed, __float_as_int(val));
        if (old == assumed) break;
    }
}

// ------------------------- 1x1 conv as GEMM: Y[n][64][4096] = W[64][256] @ X[n][256][4096] + b
__global__ void conv1x1_kernel(const float* __restrict__ X, const float* __restrict__ W,
                               const float* __restrict__ bias, float* __restrict__ Y) {
    int n  = blockIdx.y;
    int q0 = blockIdx.x * 64;
    __shared__ float Xs[64][64];   // [k][q]
    __shared__ float Ws[64][65];   // [k][co] (padded)
    int tx = threadIdx.x & 15, ty = threadIdx.x >> 4;
    float acc[4][4] = {};
    const float* Xb = X + (size_t)n * 256 * 4096;

    for (int k0 = 0; k0 < 256; k0 += 64) {
        int r  = threadIdx.x >> 4;   // 0..15
        int c4 = threadIdx.x & 15;   // 0..15
        #pragma unroll
        for (int rr = 0; rr < 64; rr += 16) {
            float4 v = *reinterpret_cast<const float4*>(Xb + (size_t)(k0 + r + rr) * 4096 + q0 + c4 * 4);
            *reinterpret_cast<float4*>(&Xs[r + rr][c4 * 4]) = v;
            int co = r + rr;
            float4 w = *reinterpret_cast<const float4*>(W + co * 256 + k0 + c4 * 4);
            Ws[c4*4+0][co] = w.x; Ws[c4*4+1][co] = w.y; Ws[c4*4+2][co] = w.z; Ws[c4*4+3][co] = w.w;
        }
        __syncthreads();
        #pragma unroll
        for (int k = 0; k < 64; k++) {
            float a[4];
            *reinterpret_cast<float4*>(a) = *reinterpret_cast<float4*>(&Xs[k][tx * 4]);
            float b0 = Ws[k][ty*4+0], b1 = Ws[k][ty*4+1], b2 = Ws[k][ty*4+2], b3 = Ws[k][ty*4+3];
            #pragma unroll
            for (int j = 0; j < 4; j++) {
                acc[0][j] = fmaf(b0, a[j], acc[0][j]);
                acc[1][j] = fmaf(b1, a[j], acc[1][j]);
                acc[2][j] = fmaf(b2, a[j], acc[2][j]);
                acc[3][j] = fmaf(b3, a[j], acc[3][j]);
            }
        }
        __syncthreads();
    }
    float* Yb = Y + (size_t)n * 64 * 4096;
    #pragma unroll
    for (int i = 0; i < 4; i++) {
        int co = ty * 4 + i;
        float bv = bias[co];
        float4 o = { acc[i][0] + bv, acc[i][1] + bv, acc[i][2] + bv, acc[i][3] + bv };
        *reinterpret_cast<float4*>(Yb + (size_t)co * 4096 + q0 + tx * 4) = o;
    }
}

// ------------------------- instance-norm stats: one block per group of length L
__global__ void in_stats(const float* __restrict__ x, float* __restrict__ mean,
                         float* __restrict__ var, int L) {
    int g = blockIdx.x;
    const float* p = x + (size_t)g * L;
    float s = 0.f, s2 = 0.f;
    for (int i = threadIdx.x; i < L; i += blockDim.x) { float v = p[i]; s += v; s2 += v * v; }
    __shared__ float shs[32], shs2[32];
    int lane = threadIdx.x & 31, w = threadIdx.x >> 5;
    #pragma unroll
    for (int o = 16; o; o >>= 1) { s += __shfl_down_sync(~0u, s, o); s2 += __shfl_down_sync(~0u, s2, o); }
    if (!lane) { shs[w] = s; shs2[w] = s2; }
    __syncthreads();
    if (w == 0) {
        int nw = blockDim.x >> 5;
        s  = (lane < nw) ? shs[lane]  : 0.f;
        s2 = (lane < nw) ? shs2[lane] : 0.f;
        #pragma unroll
        for (int o = 16; o; o >>= 1) { s += __shfl_down_sync(~0u, s, o); s2 += __shfl_down_sync(~0u, s2, o); }
        if (!lane) { float m = s / L; mean[g] = m; var[g] = fmaxf(s2 / L - m * m, 0.f); }
    }
}

// ------------------------- elementwise IN-normalize + leaky (generic)
__global__ void apply_in_leaky(const float* __restrict__ x, const float* __restrict__ mean,
                               const float* __restrict__ var, float* __restrict__ out,
                               int L, int total) {
    int idx = blockIdx.x * blockDim.x + threadIdx.x;
    if (idx >= total) return;
    int g = idx / L;
    float v = (x[idx] - mean[g]) * rsqrtf(var[g] + EPSV);
    out[idx] = v >= 0.f ? v : 0.2f * v;
}

// ------------------------- fa/fb: normalize+leaky in place, also emit channel mean of result
__global__ void apply_in_leaky_sum(float* __restrict__ x, const float* __restrict__ mean,
                                   const float* __restrict__ var, float* __restrict__ csum) {
    int g = blockIdx.x;
    float* p = x + (size_t)g * 4096;
    float m = mean[g], inv = rsqrtf(var[g] + EPSV);
    float s = 0.f;
    for (int i = threadIdx.x; i < 4096; i += blockDim.x) {
        float v = (p[i] - m) * inv;
        v = v >= 0.f ? v : 0.2f * v;
        p[i] = v; s += v;
    }
    __shared__ float shs[32];
    int lane = threadIdx.x & 31, w = threadIdx.x >> 5;
    #pragma unroll
    for (int o = 16; o; o >>= 1) s += __shfl_down_sync(~0u, s, o);
    if (!lane) shs[w] = s;
    __syncthreads();
    if (w == 0) {
        int nw = blockDim.x >> 5;
        s = (lane < nw) ? shs[lane] : 0.f;
        #pragma unroll
        for (int o = 16; o; o >>= 1) s += __shfl_down_sync(~0u, s, o);
        if (!lane) csum[g] = s * (1.f / 4096.f);
    }
}

// ------------------------- per-position (over 64 channels) mean-sub + L2 normalize
__global__ void posnorm(const float* __restrict__ z, const float* __restrict__ cm,
                        float* __restrict__ out) {
    int idx = blockIdx.x * blockDim.x + threadIdx.x;   // 0..8191
    int n = idx >> 12, pq = idx & 4095;
    const float* zb = z + (size_t)n * 64 * 4096 + pq;
    const float* cmb = cm + n * 64;
    float ss = 0.f;
    #pragma unroll
    for (int c = 0; c < 64; c++) { float v = zb[(size_t)c * 4096] - cmb[c]; ss += v * v; }
    float inv = 1.f / (sqrtf(ss) + EPSV);
    float* ob = out + (size_t)n * 64 * 4096 + pq;
    #pragma unroll
    for (int c = 0; c < 64; c++) ob[(size_t)c * 4096] = (zb[(size_t)c * 4096] - cmb[c]) * inv;
}

// ------------------------- small 3x3 conv (3ch->3ch), reflect or zero pad, pad=1
__global__ void conv3x3(const float* __restrict__ in, const float* __restrict__ W,
                        const float* __restrict__ bias, float* __restrict__ out,
                        int H, int Wi, int Ho, int Wo, int stride, int reflect) {
    int idx = blockIdx.x * blockDim.x + threadIdx.x;
    int total = 2 * 3 * Ho * Wo;
    if (idx >= total) return;
    int wo = idx % Wo; int t = idx / Wo;
    int ho = t % Ho;   t /= Ho;
    int co = t % 3;    int n = t / 3;
    float acc = bias[co];
    const float* inb = in + (size_t)n * 3 * H * Wi;
    #pragma unroll
    for (int ci = 0; ci < 3; ci++) {
        const float* ip = inb + (size_t)ci * H * Wi;
        #pragma unroll
        for (int kh = 0; kh < 3; kh++) {
            int hi = ho * stride + kh - 1;
            if (reflect) { hi = hi < 0 ? -hi : (hi >= H ? 2 * H - 2 - hi : hi); }
            else if (hi < 0 || hi >= H) continue;
            #pragma unroll
            for (int kw = 0; kw < 3; kw++) {
                int wv = wo * stride + kw - 1;
                if (reflect) { wv = wv < 0 ? -wv : (wv >= Wi ? 2 * Wi - 2 - wv : wv); }
                else if (wv < 0 || wv >= Wi) continue;
                acc = fmaf(ip[(size_t)hi * Wi + wv], W[((co * 3 + ci) * 3 + kh) * 3 + kw], acc);
            }
        }
    }
    out[idx] = acc;
}

// ------------------------- bilinear 2x upsample, align_corners=True
__global__ void up2x(const float* __restrict__ in, float* __restrict__ out, int S) {
    int O = 2 * S;
    int idx = blockIdx.x * blockDim.x + threadIdx.x;
    int total = 2 * 3 * O * O;
    if (idx >= total) return;
    int wo = idx % O; int t = idx / O;
    int ho = t % O;   t /= O;   // t = n*3 + c
    float r = (float)(S - 1) / (float)(O - 1);
    float ph = ho * r, pw = wo * r;
    int h0 = (int)floorf(ph), w0 = (int)floorf(pw);
    float fh = ph - h0, fw = pw - w0;
    int h1 = min(h0 + 1, S - 1), w1 = min(w0 + 1, S - 1);
    const float* ib = in + (size_t)t * S * S;
    float v = ib[h0 * S + w0] * (1.f - fh) * (1.f - fw)
            + ib[h1 * S + w0] * fh * (1.f - fw)
            + ib[h0 * S + w1] * (1.f - fh) * fw
            + ib[h1 * S + w1] * fh * fw;
    out[idx] = v;
}

__global__ void init_neg_inf(float* __restrict__ x, int nx) {
    int i = blockIdx.x * blockDim.x + threadIdx.x;
    if (i < nx) x[i] = -INFINITY;
}

// ------------------------- energy GEMM: E[n][p][q] = ALPHA * sum_c fb[n][c][p]*fa[n][c][q]
// 128x128 block tile, 8x8 microtile, K=64 resident. Also per-column (q) max -> atomicMaxF.
__global__ void energy_kernel(const float* __restrict__ fan, const float* __restrict__ fbn,
                              float* __restrict__ energy, float* __restrict__ colmax) {
    extern __shared__ float sm[];
    float* As = sm;             // [64][128]  fa over q
    float* Bs = sm + 64 * 128;  // [64][128]  fb over p
    float* red = sm + 2 * 64 * 128; // [16][128]
    int n = blockIdx.z;
    int q0 = blockIdx.x * 128, p0 = blockIdx.y * 128;
    int tx = threadIdx.x & 15, ty = threadIdx.x >> 4;
    const float* A = fan + (size_t)n * 64 * 4096;
    const float* B = fbn + (size_t)n * 64 * 4096;
    {
        int r = threadIdx.x >> 5;   // 0..7
        int c4 = threadIdx.x & 31;  // 0..31
        #pragma unroll
        for (int rr = 0; rr < 64; rr += 8) {
            *reinterpret_cast<float4*>(&As[(r + rr) * 128 + c4 * 4]) =
                *reinterpret_cast<const float4*>(A + (size_t)(r + rr) * 4096 + q0 + c4 * 4);
            *reinterpret_cast<float4*>(&Bs[(r + rr) * 128 + c4 * 4]) =
                *reinterpret_cast<const float4*>(B + (size_t)(r + rr) * 4096 + p0 + c4 * 4);
        }
    }
    __syncthreads();
    float acc[8][8] = {};
    #pragma unroll
    for (int k = 0; k < 64; k++) {
        float a[8], b[8];
        *reinterpret_cast<float4*>(&a[0]) = *reinterpret_cast<float4*>(&As[k * 128 + tx * 8]);
        *reinterpret_cast<float4*>(&a[4]) = *reinterpret_cast<float4*>(&As[k * 128 + tx * 8 + 4]);
        *reinterpret_cast<float4*>(&b[0]) = *reinterpret_cast<float4*>(&Bs[k * 128 + ty * 8]);
        *reinterpret_cast<float4*>(&b[4]) = *reinterpret_cast<float4*>(&Bs[k * 128 + ty * 8 + 4]);
        #pragma unroll
        for (int i = 0; i < 8; i++)
            #pragma unroll
            for (int j = 0; j < 8; j++)
                acc[i][j] = fmaf(b[i], a[j], acc[i][j]);
    }
    float* E = energy + (size_t)n * 4096 * 4096;
    float cmax[8];
    #pragma unroll
    for (int j = 0; j < 8; j++) cmax[j] = -INFINITY;
    #pragma unroll
    for (int i = 0; i < 8; i++) {
        int p = p0 + ty * 8 + i;
        float o[8];
        #pragma unroll
        for (int j = 0; j < 8; j++) { o[j] = acc[i][j] * ALPHAV; cmax[j] = fmaxf(cmax[j], o[j]); }
        *reinterpret_cast<float4*>(E + (size_t)p * 4096 + q0 + tx * 8)     = *reinterpret_cast<float4*>(&o[0]);
        *reinterpret_cast<float4*>(E + (size_t)p * 4096 + q0 + tx * 8 + 4) = *reinterpret_cast<float4*>(&o[4]);
    }
    #pragma unroll
    for (int j = 0; j < 8; j++) red[ty * 128 + tx * 8 + j] = cmax[j];
    __syncthreads();
    if (threadIdx.x < 128) {
        float m = -INFINITY;
        #pragma unroll
        for (int r = 0; r < 16; r++) m = fmaxf(m, red[r * 128 + threadIdx.x]);
        atomicMaxF(&colmax[n * 4096 + q0 + threadIdx.x], m);
    }
}

// ------------------------- softmax column partial sums + fc_warp partial accumulation
__global__ void colsum_partial(const float* __restrict__ energy, const float* __restrict__ colmax,
                               const float* __restrict__ fc, float* __restrict__ spart,
                               float* __restrict__ apart) {
    int n = blockIdx.z;
    int q = blockIdx.x * 256 + threadIdx.x;
    int ch = blockIdx.y;               // 16 chunks of 256 rows
    int p0 = ch * 256;
    const float* E = energy + (size_t)n * 4096 * 4096;
    const float* F = fc + (size_t)n * 3 * 4096;
    float m = colmax[n * 4096 + q];
    float s = 0.f, a0 = 0.f, a1 = 0.f, a2 = 0.f;
    for (int p = p0; p < p0 + 256; p++) {
        float w = __expf(E[(size_t)p * 4096 + q] - m);
        s += w;
        a0 = fmaf(__ldg(&F[p]),        w, a0);
        a1 = fmaf(__ldg(&F[4096 + p]), w, a1);
        a2 = fmaf(__ldg(&F[8192 + p]), w, a2);
    }
    spart[(n * 16 + ch) * 4096 + q] = s;
    apart[((size_t)(n * 16 + ch) * 3 + 0) * 4096 + q] = a0;
    apart[((size_t)(n * 16 + ch) * 3 + 1) * 4096 + q] = a1;
    apart[((size_t)(n * 16 + ch) * 3 + 2) * 4096 + q] = a2;
}

__global__ void colsum_final(const float* __restrict__ spart, const float* __restrict__ apart,
                             float* __restrict__ srecip, float* __restrict__ fcw) {
    int idx = blockIdx.x * blockDim.x + threadIdx.x;   // 0..8191
    int n = idx >> 12, q = idx & 4095;
    float s = 0.f, a0 = 0.f, a1 = 0.f, a2 = 0.f;
    for (int ch = 0; ch < 16; ch++) {
        s  += spart[(n * 16 + ch) * 4096 + q];
        a0 += apart[((size_t)(n * 16 + ch) * 3 + 0) * 4096 + q];
        a1 += apart[((size_t)(n * 16 + ch) * 3 + 1) * 4096 + q];
        a2 += apart[((size_t)(n * 16 + ch) * 3 + 2) * 4096 + q];
    }
    float inv = 1.f / s;
    srecip[idx] = inv;
    fcw[(n * 3 + 0) * 4096 + q] = a0 * inv;
    fcw[(n * 3 + 1) * 4096 + q] = a1 * inv;
    fcw[(n * 3 + 2) * 4096 + q] = a2 * inv;
}

// ------------------------- normalize energy -> corr in place
__global__ void normalize_kernel(float* __restrict__ energy, const float* __restrict__ colmax,
                                 const float* __restrict__ srecip) {
    size_t i4 = (size_t)blockIdx.x * blockDim.x + threadIdx.x;
    size_t idx = i4 * 4;                    // element index, total 2*4096*4096
    const size_t per = (size_t)4096 * 4096;
    int n = (int)(idx / per);
    size_t t = idx - (size_t)n * per;
    int q = (int)(t & 4095);
    float4 e = *reinterpret_cast<float4*>(energy + idx);
    float4 mv = *reinterpret_cast<const float4*>(colmax + n * 4096 + q);
    float4 sv = *reinterpret_cast<const float4*>(srecip + n * 4096 + q);
    e.x = __expf(e.x - mv.x) * sv.x;
    e.y = __expf(e.y - mv.y) * sv.y;
    e.z = __expf(e.z - mv.z) * sv.z;
    e.w = __expf(e.w - mv.w) * sv.w;
    *reinterpret_cast<float4*>(energy + idx) = e;
}

// ------------------------- launch -------------------------
extern "C" void kernel_launch(void* const* d_in, const int* in_sizes, int n_in,
                              void* d_out, int out_size) {
    const float* fa_raw = (const float*)d_in[0];
    const float* fb_raw = (const float*)d_in[1];
    const float* fc_raw = (const float*)d_in[2];
    const float* Wa = (const float*)d_in[3];  const float* ba = (const float*)d_in[4];
    const float* Wb = (const float*)d_in[5];  const float* bb = (const float*)d_in[6];
    const float* Wc1 = (const float*)d_in[7]; const float* bc1 = (const float*)d_in[8];
    const float* Wc2 = (const float*)d_in[9]; const float* bc2 = (const float*)d_in[10];
    const float* Wu1 = (const float*)d_in[11]; const float* bu1 = (const float*)d_in[12];
    const float* Wu2 = (const float*)d_in[13]; const float* bu2 = (const float*)d_in[14];
    float* out  = (float*)d_out;
    float* corr = out + 2 * 3 * 256 * 256;   // [2][4096][4096] region

    float *p_fa, *p_fb, *p_fan, *p_fbn, *p_mA, *p_vA, *p_mB, *p_vB, *p_cmA, *p_cmB;
    float *p_fc1, *p_fc2, *p_fcw, *p_up, *p_cv, *p_ms, *p_vs, *p_colmax, *p_srecip, *p_spart, *p_apart;
    cudaGetSymbolAddress((void**)&p_fa, g_fa);     cudaGetSymbolAddress((void**)&p_fb, g_fb);
    cudaGetSymbolAddress((void**)&p_fan, g_fan);   cudaGetSymbolAddress((void**)&p_fbn, g_fbn);
    cudaGetSymbolAddress((void**)&p_mA, g_mA);     cudaGetSymbolAddress((void**)&p_vA, g_vA);
    cudaGetSymbolAddress((void**)&p_mB, g_mB);     cudaGetSymbolAddress((void**)&p_vB, g_vB);
    cudaGetSymbolAddress((void**)&p_cmA, g_cmA);   cudaGetSymbolAddress((void**)&p_cmB, g_cmB);
    cudaGetSymbolAddress((void**)&p_fc1, g_fc1);   cudaGetSymbolAddress((void**)&p_fc2, g_fc2);
    cudaGetSymbolAddress((void**)&p_fcw, g_fcw);   cudaGetSymbolAddress((void**)&p_up, g_up);
    cudaGetSymbolAddress((void**)&p_cv, g_cv);     cudaGetSymbolAddress((void**)&p_ms, g_ms);
    cudaGetSymbolAddress((void**)&p_vs, g_vs);     cudaGetSymbolAddress((void**)&p_colmax, g_colmax);
    cudaGetSymbolAddress((void**)&p_srecip, g_srecip);
    cudaGetSymbolAddress((void**)&p_spart, g_spart); cudaGetSymbolAddress((void**)&p_apart, g_apart);

    // ---- fa / fb feature path
    conv1x1_kernel<<<dim3(64, 2), 256>>>(fa_raw, Wa, ba, p_fa);
    conv1x1_kernel<<<dim3(64, 2), 256>>>(fb_raw, Wb, bb, p_fb);
    in_stats<<<128, 256>>>(p_fa, p_mA, p_vA, 4096);
    in_stats<<<128, 256>>>(p_fb, p_mB, p_vB, 4096);
    apply_in_leaky_sum<<<128, 256>>>(p_fa, p_mA, p_vA, p_cmA);
    apply_in_leaky_sum<<<128, 256>>>(p_fb, p_mB, p_vB, p_cmB);
    posnorm<<<32, 256>>>(p_fa, p_cmA, p_fan);
    posnorm<<<32, 256>>>(p_fb, p_cmB, p_fbn);

    // ---- fc path (2x strided reflect conv + IN + leaky)
    conv3x3<<<(2*3*128*128 + 255) / 256, 256>>>(fc_raw, Wc1, bc1, p_fc1, 256, 256, 128, 128, 2, 1);
    in_stats<<<6, 256>>>(p_fc1, p_ms, p_vs, 16384);
    apply_in_leaky<<<(2*3*128*128 + 255) / 256, 256>>>(p_fc1, p_ms, p_vs, p_fc1, 16384, 2*3*128*128);
    conv3x3<<<(2*3*64*64 + 255) / 256, 256>>>(p_fc1, Wc2, bc2, p_fc2, 128, 128, 64, 64, 2, 1);
    in_stats<<<6, 256>>>(p_fc2, p_ms, p_vs, 4096);
    apply_in_leaky<<<(2*3*64*64 + 255) / 256, 256>>>(p_fc2, p_ms, p_vs, p_fc2, 4096, 2*3*64*64);

    // ---- correlation: energy GEMM (+colmax), column softmax, fc_warp
    init_neg_inf<<<32, 256>>>(p_colmax, 8192);
    cudaFuncSetAttribute(energy_kernel, cudaFuncAttributeMaxDynamicSharedMemorySize, 73728);
    energy_kernel<<<dim3(32, 32, 2), 256, 73728>>>(p_fan, p_fbn, corr, p_colmax);
    colsum_partial<<<dim3(16, 16, 2), 256>>>(corr, p_colmax, p_fc2, p_spart, p_apart);
    colsum_final<<<32, 256>>>(p_spart, p_apart, p_srecip, p_fcw);
    normalize_kernel<<<32768, 256>>>(corr, p_colmax, p_srecip);

    // ---- upsample block 1: 64 -> 128
    up2x<<<(2*3*128*128 + 255) / 256, 256>>>(p_fcw, p_up, 64);
    conv3x3<<<(2*3*128*128 + 255) / 256, 256>>>(p_up, Wu1, bu1, p_cv, 128, 128, 128, 128, 1, 0);
    in_stats<<<6, 256>>>(p_cv, p_ms, p_vs, 16384);
    apply_in_leaky<<<(2*3*128*128 + 255) / 256, 256>>>(p_cv, p_ms, p_vs, p_cv, 16384, 2*3*128*128);

    // ---- upsample block 2: 128 -> 256, final IN+leaky straight into d_out
    up2x<<<(2*3*256*256 + 255) / 256, 256>>>(p_cv, p_up, 128);
    conv3x3<<<(2*3*256*256 + 255) / 256, 256>>>(p_up, Wu2, bu2, p_cv, 256, 256, 256, 256, 1, 0);
    in_stats<<<6, 256>>>(p_cv, p_ms, p_vs, 65536);
    apply_in_leaky<<<(2*3*256*256 + 255) / 256, 256>>>(p_cv, p_ms, p_vs, out, 65536, 2*3*256*256);
}

// round 6
// speedup vs baseline: 1.6402x; 1.6402x over previous
#include <cuda_runtime.h>
#include <math.h>

#define EPSV 1e-5f
typedef unsigned long long u64;

// ------------------------- scratch (device globals) -------------------------
__device__ __align__(16) float  g_fa [2*64*4096];
__device__ __align__(16) float  g_fb [2*64*4096];
__device__ __align__(16) float  g_fan[2*64*4096];
__device__ __align__(16) float  g_fbn[2*64*4096];
__device__ __align__(16) float2 g_psA[2*64*64];
__device__ __align__(16) float2 g_psB[2*64*64];
__device__ __align__(16) float  g_cmA[128], g_cmB[128];
__device__ __align__(16) float  g_fc1raw[2*3*128*128];
__device__ __align__(16) float  g_fc2raw[2*3*64*64];
__device__ __align__(16) float2 g_ps1[6*64];
__device__ __align__(16) float2 g_ps2[6*16];
__device__ __align__(16) float2 g_ps3[6*64];
__device__ __align__(16) float2 g_ps4[6*256];
__device__ __align__(16) float  g_fcw[2*3*64*64];
__device__ __align__(16) float  g_up1[2*3*128*128];
__device__ __align__(16) float  g_cv1raw[2*3*128*128];
__device__ __align__(16) float  g_up2[2*3*256*256];
__device__ __align__(16) float  g_cv2raw[2*3*256*256];
__device__ __align__(16) float  g_spart[2*32*4096];
__device__ __align__(16) float  g_apart[2*32*3*4096];
__device__ __align__(16) float  g_srecip[2*4096];

// ------------------------- 1x1 conv as GEMM + fused IN-stat partials
// Y[n][64][4096] = W[64][256] @ X[n][256][4096] + b ; pstat[(n*64+co)*64+qb] = (sum, sumsq)
__global__ void conv1x1_kernel(const float* __restrict__ X, const float* __restrict__ W,
                               const float* __restrict__ bias, float* __restrict__ Y,
                               float2* __restrict__ pstat) {
    int n  = blockIdx.y;
    int q0 = blockIdx.x * 64;
    __shared__ float Xs[64][64];
    __shared__ float Ws[64][65];
    int tx = threadIdx.x & 15, ty = threadIdx.x >> 4;
    float acc[4][4] = {};
    const float* Xb = X + (size_t)n * 256 * 4096;

    for (int k0 = 0; k0 < 256; k0 += 64) {
        int r  = threadIdx.x >> 4;
        int c4 = threadIdx.x & 15;
        #pragma unroll
        for (int rr = 0; rr < 64; rr += 16) {
            float4 v = *reinterpret_cast<const float4*>(Xb + (size_t)(k0 + r + rr) * 4096 + q0 + c4 * 4);
            *reinterpret_cast<float4*>(&Xs[r + rr][c4 * 4]) = v;
            int co = r + rr;
            float4 w = *reinterpret_cast<const float4*>(W + co * 256 + k0 + c4 * 4);
            Ws[c4*4+0][co] = w.x; Ws[c4*4+1][co] = w.y; Ws[c4*4+2][co] = w.z; Ws[c4*4+3][co] = w.w;
        }
        __syncthreads();
        #pragma unroll
        for (int k = 0; k < 64; k++) {
            float a[4];
            *reinterpret_cast<float4*>(a) = *reinterpret_cast<float4*>(&Xs[k][tx * 4]);
            float b0 = Ws[k][ty*4+0], b1 = Ws[k][ty*4+1], b2 = Ws[k][ty*4+2], b3 = Ws[k][ty*4+3];
            #pragma unroll
            for (int j = 0; j < 4; j++) {
                acc[0][j] = fmaf(b0, a[j], acc[0][j]);
                acc[1][j] = fmaf(b1, a[j], acc[1][j]);
                acc[2][j] = fmaf(b2, a[j], acc[2][j]);
                acc[3][j] = fmaf(b3, a[j], acc[3][j]);
            }
        }
        __syncthreads();
    }
    float* Yb = Y + (size_t)n * 64 * 4096;
    float ls[4], ls2[4];
    #pragma unroll
    for (int i = 0; i < 4; i++) {
        int co = ty * 4 + i;
        float bv = bias[co];
        float o0 = acc[i][0] + bv, o1 = acc[i][1] + bv, o2 = acc[i][2] + bv, o3 = acc[i][3] + bv;
        float4 o = { o0, o1, o2, o3 };
        *reinterpret_cast<float4*>(Yb + (size_t)co * 4096 + q0 + tx * 4) = o;
        ls[i]  = o0 + o1 + o2 + o3;
        ls2[i] = o0*o0 + o1*o1 + o2*o2 + o3*o3;
    }
    __syncthreads();
    float* redS  = &Xs[0][0];
    float* redS2 = redS + 1024;
    #pragma unroll
    for (int i = 0; i < 4; i++) {
        int co = ty * 4 + i;
        redS[co * 16 + tx]  = ls[i];
        redS2[co * 16 + tx] = ls2[i];
    }
    __syncthreads();
    if (threadIdx.x < 64) {
        float s = 0.f, s2 = 0.f;
        #pragma unroll
        for (int t = 0; t < 16; t++) { s += redS[threadIdx.x * 16 + t]; s2 += redS2[threadIdx.x * 16 + t]; }
        pstat[(n * 64 + threadIdx.x) * 64 + blockIdx.x] = make_float2(s, s2);
    }
}

// ------------------------- fa/fb: IN + leaky in place (stats from partials) + channel-mean of result
__global__ void apply_sum_both(float* __restrict__ fa, float* __restrict__ fb,
                               const float2* __restrict__ psA, const float2* __restrict__ psB,
                               float* __restrict__ cmA, float* __restrict__ cmB) {
    int g = blockIdx.x;               // 0..255
    int tensor = g >> 7, gc = g & 127;
    float* p = (tensor ? fb : fa) + (size_t)gc * 4096;
    const float2* ps = (tensor ? psB : psA) + gc * 64;
    __shared__ float sh_m, sh_inv, sh[8];
    int tid = threadIdx.x, lane = tid & 31, w = tid >> 5;
    if (w == 0) {
        float s = 0.f, s2 = 0.f;
        for (int t = lane; t < 64; t += 32) { float2 v = ps[t]; s += v.x; s2 += v.y; }
        #pragma unroll
        for (int o = 16; o; o >>= 1) { s += __shfl_down_sync(~0u, s, o); s2 += __shfl_down_sync(~0u, s2, o); }
        if (!lane) {
            float m = s * (1.f / 4096.f);
            float var = fmaxf(s2 * (1.f / 4096.f) - m * m, 0.f);
            sh_m = m; sh_inv = rsqrtf(var + EPSV);
        }
    }
    __syncthreads();
    float m = sh_m, inv = sh_inv, cs = 0.f;
    float4* p4 = (float4*)p;
    for (int i = tid; i < 1024; i += 256) {
        float4 v = p4[i];
        v.x = (v.x - m) * inv; v.x = v.x >= 0.f ? v.x : 0.2f * v.x;
        v.y = (v.y - m) * inv; v.y = v.y >= 0.f ? v.y : 0.2f * v.y;
        v.z = (v.z - m) * inv; v.z = v.z >= 0.f ? v.z : 0.2f * v.z;
        v.w = (v.w - m) * inv; v.w = v.w >= 0.f ? v.w : 0.2f * v.w;
        cs += v.x + v.y + v.z + v.w;
        p4[i] = v;
    }
    #pragma unroll
    for (int o = 16; o; o >>= 1) cs += __shfl_down_sync(~0u, cs, o);
    if (!lane) sh[w] = cs;
    __syncthreads();
    if (w == 0) {
        cs = (lane < 8) ? sh[lane] : 0.f;
        #pragma unroll
        for (int o = 4; o; o >>= 1) cs += __shfl_down_sync(~0u, cs, o);
        if (!lane) (tensor ? cmB : cmA)[gc] = cs * (1.f / 4096.f);
    }
}

// ------------------------- per-position channel-mean-sub + L2 normalize (both tensors)
__global__ void posnorm_both(const float* __restrict__ fa, const float* __restrict__ fb,
                             const float* __restrict__ cmA, const float* __restrict__ cmB,
                             float* __restrict__ fan, float* __restrict__ fbn) {
    int idx = blockIdx.x * 256 + threadIdx.x;       // 0..16383
    int tensor = idx >> 13, sub = idx & 8191;
    int n = sub >> 12, pq = sub & 4095;
    const float* z  = (tensor ? fb : fa) + (size_t)n * 64 * 4096 + pq;
    const float* cm = (tensor ? cmB : cmA) + n * 64;
    float* o = (tensor ? fbn : fan) + (size_t)n * 64 * 4096 + pq;
    float ss = 0.f;
    #pragma unroll
    for (int c = 0; c < 64; c++) { float v = z[(size_t)c * 4096] - cm[c]; ss += v * v; }
    float inv = 1.f / (sqrtf(ss) + EPSV);
    #pragma unroll
    for (int c = 0; c < 64; c++) o[(size_t)c * 4096] = (z[(size_t)c * 4096] - cm[c]) * inv;
}

// ------------------------- generic 3x3 conv stage (3ch->3ch) + fused stat partials
// optional norm-on-load of the input (IN+leaky from instat partials, reduced redundantly per block)
__global__ void stage_conv(const float* __restrict__ in, const float2* __restrict__ instat,
                           int npart_in, int use_norm,
                           const float* __restrict__ W, const float* __restrict__ bias,
                           float* __restrict__ outraw, float2* __restrict__ pstat,
                           int H, int Wi, int Ho, int Wo, int stride, int reflect) {
    int planeSz = Ho * Wo;
    int bpp = planeSz >> 8;
    int plane = blockIdx.x / bpp;
    int n = plane / 3, co = plane % 3;
    int tid = threadIdx.x, lane = tid & 31, w = tid >> 5;
    __shared__ float s_m[3], s_inv[3], shA[8], shB[8];
    if (use_norm && w < 3) {
        float s = 0.f, s2 = 0.f;
        for (int t = lane; t < npart_in; t += 32) {
            float2 v = instat[(n * 3 + w) * npart_in + t]; s += v.x; s2 += v.y;
        }
        #pragma unroll
        for (int o = 16; o; o >>= 1) { s += __shfl_down_sync(~0u, s, o); s2 += __shfl_down_sync(~0u, s2, o); }
        if (!lane) {
            float Lf = (float)(H * Wi);
            float m = s / Lf; float var = fmaxf(s2 / Lf - m * m, 0.f);
            s_m[w] = m; s_inv[w] = rsqrtf(var + EPSV);
        }
    }
    if (use_norm) __syncthreads();
    float mm[3], ii[3];
    if (use_norm) { mm[0]=s_m[0]; mm[1]=s_m[1]; mm[2]=s_m[2]; ii[0]=s_inv[0]; ii[1]=s_inv[1]; ii[2]=s_inv[2]; }

    int opix = (blockIdx.x % bpp) * 256 + tid;
    int ho = opix / Wo, wo = opix % Wo;
    float acc = bias[co];
    const float* inb = in + (size_t)n * 3 * H * Wi;
    #pragma unroll
    for (int ci = 0; ci < 3; ci++) {
        const float* ip = inb + (size_t)ci * H * Wi;
        #pragma unroll
        for (int kh = 0; kh < 3; kh++) {
            int hi = ho * stride + kh - 1;
            if (reflect) { hi = hi < 0 ? -hi : (hi >= H ? 2 * H - 2 - hi : hi); }
            else if (hi < 0 || hi >= H) continue;
            #pragma unroll
            for (int kw = 0; kw < 3; kw++) {
                int wv = wo * stride + kw - 1;
                if (reflect) { wv = wv < 0 ? -wv : (wv >= Wi ? 2 * Wi - 2 - wv : wv); }
                else if (wv < 0 || wv >= Wi) continue;
                float v = ip[(size_t)hi * Wi + wv];
                if (use_norm) { v = (v - mm[ci]) * ii[ci]; v = v >= 0.f ? v : 0.2f * v; }
                acc = fmaf(v, W[((co * 3 + ci) * 3 + kh) * 3 + kw], acc);
            }
        }
    }
    outraw[(size_t)plane * planeSz + opix] = acc;

    float s = acc, s2 = acc * acc;
    #pragma unroll
    for (int o = 16; o; o >>= 1) { s += __shfl_down_sync(~0u, s, o); s2 += __shfl_down_sync(~0u, s2, o); }
    if (!lane) { shA[w] = s; shB[w] = s2; }
    __syncthreads();
    if (w == 0) {
        s  = (lane < 8) ? shA[lane] : 0.f;
        s2 = (lane < 8) ? shB[lane] : 0.f;
        #pragma unroll
        for (int o = 4; o; o >>= 1) { s += __shfl_down_sync(~0u, s, o); s2 += __shfl_down_sync(~0u, s2, o); }
        if (!lane) pstat[plane * bpp + (blockIdx.x % bpp)] = make_float2(s, s2);
    }
}

// ------------------------- bilinear 2x upsample (align_corners), optional norm+leaky on load
__global__ void up2x_k(const float* __restrict__ in, const float2* __restrict__ instat,
                       int npart_in, int use_norm, float* __restrict__ out, int S) {
    int O = 2 * S;
    int planeSz = O * O;
    int bpp = planeSz >> 8;
    int plane = blockIdx.x / bpp;
    int tid = threadIdx.x, lane = tid & 31, w = tid >> 5;
    __shared__ float sh_m, sh_inv;
    if (use_norm && w == 0) {
        float s = 0.f, s2 = 0.f;
        for (int t = lane; t < npart_in; t += 32) {
            float2 v = instat[plane * npart_in + t]; s += v.x; s2 += v.y;
        }
        #pragma unroll
        for (int o = 16; o; o >>= 1) { s += __shfl_down_sync(~0u, s, o); s2 += __shfl_down_sync(~0u, s2, o); }
        if (!lane) {
            float Lf = (float)(S * S);
            float m = s / Lf; float var = fmaxf(s2 / Lf - m * m, 0.f);
            sh_m = m; sh_inv = rsqrtf(var + EPSV);
        }
    }
    if (use_norm) __syncthreads();
    float m = use_norm ? sh_m : 0.f, inv = use_norm ? sh_inv : 1.f;

    int opix = (blockIdx.x % bpp) * 256 + tid;
    int ho = opix / O, wo = opix % O;
    float r = (float)(S - 1) / (float)(O - 1);
    float ph = ho * r, pw = wo * r;
    int h0 = (int)floorf(ph), w0 = (int)floorf(pw);
    float fh = ph - h0, fw = pw - w0;
    int h1 = min(h0 + 1, S - 1), w1 = min(w0 + 1, S - 1);
    const float* ib = in + (size_t)plane * S * S;
    float v00 = ib[h0 * S + w0], v10 = ib[h1 * S + w0], v01 = ib[h0 * S + w1], v11 = ib[h1 * S + w1];
    if (use_norm) {
        v00 = (v00 - m) * inv; v00 = v00 >= 0.f ? v00 : 0.2f * v00;
        v10 = (v10 - m) * inv; v10 = v10 >= 0.f ? v10 : 0.2f * v10;
        v01 = (v01 - m) * inv; v01 = v01 >= 0.f ? v01 : 0.2f * v01;
        v11 = (v11 - m) * inv; v11 = v11 >= 0.f ? v11 : 0.2f * v11;
    }
    float v = v00 * (1.f - fh) * (1.f - fw) + v10 * fh * (1.f - fw)
            + v01 * (1.f - fh) * fw + v11 * fh * fw;
    out[(size_t)plane * planeSz + opix] = v;
}

// ------------------------- final IN + leaky -> d_out
__global__ void final_apply(const float* __restrict__ raw, const float2* __restrict__ ps,
                            float* __restrict__ out) {
    int plane = blockIdx.x >> 8;              // 256 blocks/plane, plane = 65536 elems
    int tid = threadIdx.x, lane = tid & 31, w = tid >> 5;
    __shared__ float shA[8], shB[8], sh_m, sh_inv;
    float2 v2 = ps[plane * 256 + tid];
    float s = v2.x, s2 = v2.y;
    #pragma unroll
    for (int o = 16; o; o >>= 1) { s += __shfl_down_sync(~0u, s, o); s2 += __shfl_down_sync(~0u, s2, o); }
    if (!lane) { shA[w] = s; shB[w] = s2; }
    __syncthreads();
    if (w == 0) {
        s  = (lane < 8) ? shA[lane] : 0.f;
        s2 = (lane < 8) ? shB[lane] : 0.f;
        #pragma unroll
        for (int o = 4; o; o >>= 1) { s += __shfl_down_sync(~0u, s, o); s2 += __shfl_down_sync(~0u, s2, o); }
        if (!lane) {
            float m = s * (1.f / 65536.f);
            float var = fmaxf(s2 * (1.f / 65536.f) - m * m, 0.f);
            sh_m = m; sh_inv = rsqrtf(var + EPSV);
        }
    }
    __syncthreads();
    int idx = blockIdx.x * 256 + tid;
    float x = (raw[idx] - sh_m) * sh_inv;
    out[idx] = x >= 0.f ? x : 0.2f * x;
}

// ------------------------- energy GEMM with f32x2 FFMA + fused exp/colsum/fc-warp partials
// E'[n][p][q] = exp(100*dot - 50); spart[(n*32+pb)*4096+q] = sum_p E';
// apart[((n*32+pb)*3+c)*4096+q] = sum_p fc[c][p]*E'
__global__ void __launch_bounds__(256, 2)
energy_kernel(const float* __restrict__ fan, const float* __restrict__ fbn,
              const float* __restrict__ fc2raw, const float2* __restrict__ ps2,
              float* __restrict__ E, float* __restrict__ spart, float* __restrict__ apart) {
    extern __shared__ float sm[];
    float*  As  = sm;                      // [64][128]
    float*  Bs  = sm + 8192;               // [64][128]
    float*  fcs = sm + 16384;              // [3][128]
    float2* red = (float2*)(sm + 16768);   // [16][128]
    __shared__ float s_m[3], s_inv[3];

    int n = blockIdx.z, q0 = blockIdx.x * 128, p0 = blockIdx.y * 128, pb = blockIdx.y;
    int tid = threadIdx.x, tx = tid & 15, ty = tid >> 4, lane = tid & 31, w = tid >> 5;
    const float* A = fan + (size_t)n * 64 * 4096;
    const float* B = fbn + (size_t)n * 64 * 4096;

    // redundant reduce of fc2 IN stats (16 partials per channel)
    if (w < 3) {
        float s = 0.f, s2 = 0.f;
        if (lane < 16) { float2 v = ps2[(n * 3 + w) * 16 + lane]; s = v.x; s2 = v.y; }
        #pragma unroll
        for (int o = 16; o; o >>= 1) { s += __shfl_down_sync(~0u, s, o); s2 += __shfl_down_sync(~0u, s2, o); }
        if (!lane) {
            float m = s * (1.f / 4096.f);
            float var = fmaxf(s2 * (1.f / 4096.f) - m * m, 0.f);
            s_m[w] = m; s_inv[w] = rsqrtf(var + EPSV);
        }
    }
    // tile loads
    {
        int r = tid >> 5, c4 = tid & 31;
        #pragma unroll
        for (int rr = 0; rr < 64; rr += 8) {
            *reinterpret_cast<float4*>(&As[(r + rr) * 128 + c4 * 4]) =
                *reinterpret_cast<const float4*>(A + (size_t)(r + rr) * 4096 + q0 + c4 * 4);
            *reinterpret_cast<float4*>(&Bs[(r + rr) * 128 + c4 * 4]) =
                *reinterpret_cast<const float4*>(B + (size_t)(r + rr) * 4096 + p0 + c4 * 4);
        }
    }
    __syncthreads();
    // normalized fc tile (needs s_m/s_inv, valid after the sync).
    // 384 entries, 256 threads -> strided loop (BUG FIX: previously tid<384 never covered c=2)
    for (int t = tid; t < 384; t += 256) {
        int c = t >> 7, i = t & 127;
        float v = fc2raw[((size_t)n * 3 + c) * 4096 + p0 + i];
        v = (v - s_m[c]) * s_inv[c];
        fcs[c * 128 + i] = v >= 0.f ? v : 0.2f * v;
    }

    u64 acc2[8][4] = {};
    #pragma unroll 16
    for (int k = 0; k < 64; k++) {
        u64 a2[4];
        #pragma unroll
        for (int j = 0; j < 4; j++)
            a2[j] = *reinterpret_cast<const u64*>(&As[k * 128 + tx * 8 + j * 2]);
        float4 bv0 = *reinterpret_cast<const float4*>(&Bs[k * 128 + ty * 8]);
        float4 bv1 = *reinterpret_cast<const float4*>(&Bs[k * 128 + ty * 8 + 4]);
        float bf[8] = { bv0.x, bv0.y, bv0.z, bv0.w, bv1.x, bv1.y, bv1.z, bv1.w };
        #pragma unroll
        for (int i = 0; i < 8; i++) {
            u64 b2;
            asm("mov.b64 %0, {%1, %1};" : "=l"(b2) : "f"(bf[i]));
            #pragma unroll
            for (int j = 0; j < 4; j++)
                asm("fma.rn.f32x2 %0, %1, %2, %0;" : "+l"(acc2[i][j]) : "l"(b2), "l"(a2[j]));
        }
    }
    __syncthreads();   // fcs visible to all

    float* Eb = E + (size_t)n * 4096 * 4096;
    float sC[8] = {}, a0C[8] = {}, a1C[8] = {}, a2C[8] = {};
    #pragma unroll
    for (int i = 0; i < 8; i++) {
        int prow = ty * 8 + i;
        float f0 = fcs[prow], f1 = fcs[128 + prow], f2 = fcs[256 + prow];
        float o[8];
        #pragma unroll
        for (int j = 0; j < 4; j++) {
            float lo, hi;
            asm("mov.b64 {%0, %1}, %2;" : "=f"(lo), "=f"(hi) : "l"(acc2[i][j]));
            o[2 * j] = lo; o[2 * j + 1] = hi;
        }
        #pragma unroll
        for (int j = 0; j < 8; j++) {
            float e = __expf(fmaf(100.f, o[j], -50.f));
            o[j] = e;
            sC[j] += e;
            a0C[j] = fmaf(f0, e, a0C[j]);
            a1C[j] = fmaf(f1, e, a1C[j]);
            a2C[j] = fmaf(f2, e, a2C[j]);
        }
        size_t rowoff = (size_t)(p0 + prow) * 4096 + q0 + tx * 8;
        *reinterpret_cast<float4*>(Eb + rowoff)     = make_float4(o[0], o[1], o[2], o[3]);
        *reinterpret_cast<float4*>(Eb + rowoff + 4) = make_float4(o[4], o[5], o[6], o[7]);
    }
    // column reductions over the block's 128 rows: round 1 (s, a0)
    #pragma unroll
    for (int j = 0; j < 8; j++) red[ty * 128 + tx * 8 + j] = make_float2(sC[j], a0C[j]);
    __syncthreads();
    if (tid < 128) {
        float rs = 0.f, ra = 0.f;
        #pragma unroll
        for (int r = 0; r < 16; r++) { float2 v = red[r * 128 + tid]; rs += v.x; ra += v.y; }
        size_t base = (size_t)(n * 32) + pb;
        spart[base * 4096 + q0 + tid] = rs;
        apart[(base * 3 + 0) * 4096 + q0 + tid] = ra;
    }
    __syncthreads();
    // round 2 (a1, a2)
    #pragma unroll
    for (int j = 0; j < 8; j++) red[ty * 128 + tx * 8 + j] = make_float2(a1C[j], a2C[j]);
    __syncthreads();
    if (tid < 128) {
        float r1 = 0.f, r2 = 0.f;
        #pragma unroll
        for (int r = 0; r < 16; r++) { float2 v = red[r * 128 + tid]; r1 += v.x; r2 += v.y; }
        size_t base = (size_t)(n * 32) + pb;
        apart[(base * 3 + 1) * 4096 + q0 + tid] = r1;
        apart[(base * 3 + 2) * 4096 + q0 + tid] = r2;
    }
}

// ------------------------- reduce partials -> 1/sum and fc_warp
__global__ void colsum_final(const float* __restrict__ spart, const float* __restrict__ apart,
                             float* __restrict__ srecip, float* __restrict__ fcw) {
    int idx = blockIdx.x * 256 + threadIdx.x;   // 0..8191
    int n = idx >> 12, q = idx & 4095;
    float s = 0.f, a0 = 0.f, a1 = 0.f, a2 = 0.f;
    for (int pb = 0; pb < 32; pb++) {
        size_t base = (size_t)(n * 32) + pb;
        s  += spart[base * 4096 + q];
        a0 += apart[(base * 3 + 0) * 4096 + q];
        a1 += apart[(base * 3 + 1) * 4096 + q];
        a2 += apart[(base * 3 + 2) * 4096 + q];
    }
    float inv = 1.f / s;
    srecip[idx] = inv;
    fcw[((size_t)n * 3 + 0) * 4096 + q] = a0 * inv;
    fcw[((size_t)n * 3 + 1) * 4096 + q] = a1 * inv;
    fcw[((size_t)n * 3 + 2) * 4096 + q] = a2 * inv;
}

// ------------------------- scale E' by 1/sum -> corr (in place)
__global__ void scale_kernel(float* __restrict__ E, const float* __restrict__ srecip) {
    size_t i4 = (size_t)blockIdx.x * blockDim.x + threadIdx.x;
    size_t idx = i4 * 4;
    int n = (int)(i4 >> 22);
    int q = (int)(idx & 4095);
    float4 e = *reinterpret_cast<float4*>(E + idx);
    float4 sv = *reinterpret_cast<const float4*>(srecip + n * 4096 + q);
    e.x *= sv.x; e.y *= sv.y; e.z *= sv.z; e.w *= sv.w;
    *reinterpret_cast<float4*>(E + idx) = e;
}

// ------------------------- launch -------------------------
extern "C" void kernel_launch(void* const* d_in, const int* in_sizes, int n_in,
                              void* d_out, int out_size) {
    const float* fa_raw = (const float*)d_in[0];
    const float* fb_raw = (const float*)d_in[1];
    const float* fc_raw = (const float*)d_in[2];
    const float* Wa = (const float*)d_in[3];   const float* ba = (const float*)d_in[4];
    const float* Wb = (const float*)d_in[5];   const float* bb = (const float*)d_in[6];
    const float* Wc1 = (const float*)d_in[7];  const float* bc1 = (const float*)d_in[8];
    const float* Wc2 = (const float*)d_in[9];  const float* bc2 = (const float*)d_in[10];
    const float* Wu1 = (const float*)d_in[11]; const float* bu1 = (const float*)d_in[12];
    const float* Wu2 = (const float*)d_in[13]; const float* bu2 = (const float*)d_in[14];
    float* out  = (float*)d_out;
    float* corr = out + 2 * 3 * 256 * 256;

    float *p_fa, *p_fb, *p_fan, *p_fbn, *p_cmA, *p_cmB;
    float *p_fc1raw, *p_fc2raw, *p_fcw, *p_up1, *p_cv1raw, *p_up2, *p_cv2raw;
    float *p_spart, *p_apart, *p_srecip;
    float2 *p_psA, *p_psB, *p_ps1, *p_ps2, *p_ps3, *p_ps4;
    cudaGetSymbolAddress((void**)&p_fa, g_fa);       cudaGetSymbolAddress((void**)&p_fb, g_fb);
    cudaGetSymbolAddress((void**)&p_fan, g_fan);     cudaGetSymbolAddress((void**)&p_fbn, g_fbn);
    cudaGetSymbolAddress((void**)&p_psA, g_psA);     cudaGetSymbolAddress((void**)&p_psB, g_psB);
    cudaGetSymbolAddress((void**)&p_cmA, g_cmA);     cudaGetSymbolAddress((void**)&p_cmB, g_cmB);
    cudaGetSymbolAddress((void**)&p_fc1raw, g_fc1raw); cudaGetSymbolAddress((void**)&p_fc2raw, g_fc2raw);
    cudaGetSymbolAddress((void**)&p_ps1, g_ps1);     cudaGetSymbolAddress((void**)&p_ps2, g_ps2);
    cudaGetSymbolAddress((void**)&p_ps3, g_ps3);     cudaGetSymbolAddress((void**)&p_ps4, g_ps4);
    cudaGetSymbolAddress((void**)&p_fcw, g_fcw);     cudaGetSymbolAddress((void**)&p_up1, g_up1);
    cudaGetSymbolAddress((void**)&p_cv1raw, g_cv1raw); cudaGetSymbolAddress((void**)&p_up2, g_up2);
    cudaGetSymbolAddress((void**)&p_cv2raw, g_cv2raw);
    cudaGetSymbolAddress((void**)&p_spart, g_spart); cudaGetSymbolAddress((void**)&p_apart, g_apart);
    cudaGetSymbolAddress((void**)&p_srecip, g_srecip);

    // fa/fb feature path
    conv1x1_kernel<<<dim3(64, 2), 256>>>(fa_raw, Wa, ba, p_fa, p_psA);
    conv1x1_kernel<<<dim3(64, 2), 256>>>(fb_raw, Wb, bb, p_fb, p_psB);
    apply_sum_both<<<256, 256>>>(p_fa, p_fb, p_psA, p_psB, p_cmA, p_cmB);
    posnorm_both<<<64, 256>>>(p_fa, p_fb, p_cmA, p_cmB, p_fan, p_fbn);

    // fc path
    stage_conv<<<384, 256>>>(fc_raw, nullptr, 0, 0, Wc1, bc1, p_fc1raw, p_ps1,
                             256, 256, 128, 128, 2, 1);
    stage_conv<<<96, 256>>>(p_fc1raw, p_ps1, 64, 1, Wc2, bc2, p_fc2raw, p_ps2,
                            128, 128, 64, 64, 2, 1);

    // correlation: fused GEMM + exp + partials; then reduce; then scale
    cudaFuncSetAttribute(energy_kernel, cudaFuncAttributeMaxDynamicSharedMemorySize, 83456);
    energy_kernel<<<dim3(32, 32, 2), 256, 83456>>>(p_fan, p_fbn, p_fc2raw, p_ps2,
                                                   corr, p_spart, p_apart);
    colsum_final<<<32, 256>>>(p_spart, p_apart, p_srecip, p_fcw);
    scale_kernel<<<32768, 256>>>(corr, p_srecip);

    // upsample block 1: 64 -> 128
    up2x_k<<<384, 256>>>(p_fcw, nullptr, 0, 0, p_up1, 64);
    stage_conv<<<384, 256>>>(p_up1, nullptr, 0, 0, Wu1, bu1, p_cv1raw, p_ps3,
                             128, 128, 128, 128, 1, 0);
    // upsample block 2: 128 -> 256 (norm+leaky of cv1 fused into upsample load)
    up2x_k<<<1536, 256>>>(p_cv1raw, p_ps3, 64, 1, p_up2, 128);
    stage_conv<<<1536, 256>>>(p_up2, nullptr, 0, 0, Wu2, bu2, p_cv2raw, p_ps4,
                              256, 256, 256, 256, 1, 0);
    final_apply<<<1536, 256>>>(p_cv2raw, p_ps4, out);
}

// round 10
// speedup vs baseline: 1.6666x; 1.0161x over previous
#include <cuda_runtime.h>
#include <cuda_bf16.h>
#include <math.h>
#include <stdint.h>

#define EPSV 1e-5f
typedef unsigned long long u64;

// ------------------------- scratch (device globals) -------------------------
__device__ __align__(16) float  g_fa [2*64*4096];
__device__ __align__(16) float  g_fb [2*64*4096];
__device__ __align__(16) float2 g_psA[2*64*64];
__device__ __align__(16) float2 g_psB[2*64*64];
__device__ __align__(16) float  g_cmA[128], g_cmB[128];
__device__ __align__(16) __nv_bfloat16 g_axh[2*4096*64];  // fa hi, position-major
__device__ __align__(16) __nv_bfloat16 g_axl[2*4096*64];  // fa lo
__device__ __align__(16) __nv_bfloat16 g_bxh[2*4096*64];  // fb hi
__device__ __align__(16) __nv_bfloat16 g_bxl[2*4096*64];  // fb lo
__device__ __align__(16) float  g_fc1raw[2*3*128*128];
__device__ __align__(16) float  g_fc2raw[2*3*64*64];
__device__ __align__(16) float2 g_ps1[6*64];
__device__ __align__(16) float2 g_ps2[6*16];
__device__ __align__(16) float2 g_ps3[6*64];
__device__ __align__(16) float2 g_ps4[6*256];
__device__ __align__(16) float  g_fcw[2*3*64*64];
__device__ __align__(16) float  g_up1[2*3*128*128];
__device__ __align__(16) float  g_cv1raw[2*3*128*128];
__device__ __align__(16) float  g_up2[2*3*256*256];
__device__ __align__(16) float  g_cv2raw[2*3*256*256];
__device__ __align__(16) float  g_spart[2*32*4096];
__device__ __align__(16) float  g_apart[2*32*3*4096];
__device__ __align__(16) float  g_srecip[2*4096];

// ------------------------- helpers -------------------------
__device__ __forceinline__ uint32_t smem_u32(const void* p) {
    uint32_t a;
    asm("{ .reg .u64 t; cvta.to.shared.u64 t, %1; cvt.u32.u64 %0, t; }" : "=r"(a) : "l"(p));
    return a;
}
static __device__ __forceinline__ uint32_t sw128(uint32_t o) { return o ^ ((o >> 3) & 0x70); }

__device__ __forceinline__ void ldsm_x4(uint32_t* r, uint32_t addr) {
    asm volatile("ldmatrix.sync.aligned.m8n8.x4.shared.b16 {%0,%1,%2,%3}, [%4];"
                 : "=r"(r[0]), "=r"(r[1]), "=r"(r[2]), "=r"(r[3]) : "r"(addr));
}
__device__ __forceinline__ void mma16816(float* d, const uint32_t* a, const uint32_t* b) {
    asm volatile("mma.sync.aligned.m16n8k16.row.col.f32.bf16.bf16.f32 "
                 "{%0,%1,%2,%3}, {%4,%5,%6,%7}, {%8,%9}, {%0,%1,%2,%3};"
                 : "+f"(d[0]), "+f"(d[1]), "+f"(d[2]), "+f"(d[3])
                 : "r"(a[0]), "r"(a[1]), "r"(a[2]), "r"(a[3]), "r"(b[0]), "r"(b[1]));
}

// ------------------------- 1x1 conv as GEMM + fused IN-stat partials
__global__ void conv1x1_kernel(const float* __restrict__ X, const float* __restrict__ W,
                               const float* __restrict__ bias, float* __restrict__ Y,
                               float2* __restrict__ pstat) {
    int n  = blockIdx.y;
    int q0 = blockIdx.x * 64;
    __shared__ float Xs[64][64];
    __shared__ float Ws[64][65];
    int tx = threadIdx.x & 15, ty = threadIdx.x >> 4;
    float acc[4][4] = {};
    const float* Xb = X + (size_t)n * 256 * 4096;

    for (int k0 = 0; k0 < 256; k0 += 64) {
        int r  = threadIdx.x >> 4;
        int c4 = threadIdx.x & 15;
        #pragma unroll
        for (int rr = 0; rr < 64; rr += 16) {
            float4 v = *reinterpret_cast<const float4*>(Xb + (size_t)(k0 + r + rr) * 4096 + q0 + c4 * 4);
            *reinterpret_cast<float4*>(&Xs[r + rr][c4 * 4]) = v;
            int co = r + rr;
            float4 w = *reinterpret_cast<const float4*>(W + co * 256 + k0 + c4 * 4);
            Ws[c4*4+0][co] = w.x; Ws[c4*4+1][co] = w.y; Ws[c4*4+2][co] = w.z; Ws[c4*4+3][co] = w.w;
        }
        __syncthreads();
        #pragma unroll
        for (int k = 0; k < 64; k++) {
            float a[4];
            *reinterpret_cast<float4*>(a) = *reinterpret_cast<float4*>(&Xs[k][tx * 4]);
            float b0 = Ws[k][ty*4+0], b1 = Ws[k][ty*4+1], b2 = Ws[k][ty*4+2], b3 = Ws[k][ty*4+3];
            #pragma unroll
            for (int j = 0; j < 4; j++) {
                acc[0][j] = fmaf(b0, a[j], acc[0][j]);
                acc[1][j] = fmaf(b1, a[j], acc[1][j]);
                acc[2][j] = fmaf(b2, a[j], acc[2][j]);
                acc[3][j] = fmaf(b3, a[j], acc[3][j]);
            }
        }
        __syncthreads();
    }
    float* Yb = Y + (size_t)n * 64 * 4096;
    float ls[4], ls2[4];
    #pragma unroll
    for (int i = 0; i < 4; i++) {
        int co = ty * 4 + i;
        float bv = bias[co];
        float o0 = acc[i][0] + bv, o1 = acc[i][1] + bv, o2 = acc[i][2] + bv, o3 = acc[i][3] + bv;
        float4 o = { o0, o1, o2, o3 };
        *reinterpret_cast<float4*>(Yb + (size_t)co * 4096 + q0 + tx * 4) = o;
        ls[i]  = o0 + o1 + o2 + o3;
        ls2[i] = o0*o0 + o1*o1 + o2*o2 + o3*o3;
    }
    __syncthreads();
    float* redS  = &Xs[0][0];
    float* redS2 = redS + 1024;
    #pragma unroll
    for (int i = 0; i < 4; i++) {
        int co = ty * 4 + i;
        redS[co * 16 + tx]  = ls[i];
        redS2[co * 16 + tx] = ls2[i];
    }
    __syncthreads();
    if (threadIdx.x < 64) {
        float s = 0.f, s2 = 0.f;
        #pragma unroll
        for (int t = 0; t < 16; t++) { s += redS[threadIdx.x * 16 + t]; s2 += redS2[threadIdx.x * 16 + t]; }
        pstat[(n * 64 + threadIdx.x) * 64 + blockIdx.x] = make_float2(s, s2);
    }
}

// ------------------------- fa/fb: IN + leaky in place + channel-mean of result
__global__ void apply_sum_both(float* __restrict__ fa, float* __restrict__ fb,
                               const float2* __restrict__ psA, const float2* __restrict__ psB,
                               float* __restrict__ cmA, float* __restrict__ cmB) {
    int g = blockIdx.x;
    int tensor = g >> 7, gc = g & 127;
    float* p = (tensor ? fb : fa) + (size_t)gc * 4096;
    const float2* ps = (tensor ? psB : psA) + gc * 64;
    __shared__ float sh_m, sh_inv, sh[8];
    int tid = threadIdx.x, lane = tid & 31, w = tid >> 5;
    if (w == 0) {
        float s = 0.f, s2 = 0.f;
        for (int t = lane; t < 64; t += 32) { float2 v = ps[t]; s += v.x; s2 += v.y; }
        #pragma unroll
        for (int o = 16; o; o >>= 1) { s += __shfl_down_sync(~0u, s, o); s2 += __shfl_down_sync(~0u, s2, o); }
        if (!lane) {
            float m = s * (1.f / 4096.f);
            float var = fmaxf(s2 * (1.f / 4096.f) - m * m, 0.f);
            sh_m = m; sh_inv = rsqrtf(var + EPSV);
        }
    }
    __syncthreads();
    float m = sh_m, inv = sh_inv, cs = 0.f;
    float4* p4 = (float4*)p;
    for (int i = tid; i < 1024; i += 256) {
        float4 v = p4[i];
        v.x = (v.x - m) * inv; v.x = v.x >= 0.f ? v.x : 0.2f * v.x;
        v.y = (v.y - m) * inv; v.y = v.y >= 0.f ? v.y : 0.2f * v.y;
        v.z = (v.z - m) * inv; v.z = v.z >= 0.f ? v.z : 0.2f * v.z;
        v.w = (v.w - m) * inv; v.w = v.w >= 0.f ? v.w : 0.2f * v.w;
        cs += v.x + v.y + v.z + v.w;
        p4[i] = v;
    }
    #pragma unroll
    for (int o = 16; o; o >>= 1) cs += __shfl_down_sync(~0u, cs, o);
    if (!lane) sh[w] = cs;
    __syncthreads();
    if (w == 0) {
        cs = (lane < 8) ? sh[lane] : 0.f;
        #pragma unroll
        for (int o = 4; o; o >>= 1) cs += __shfl_down_sync(~0u, cs, o);
        if (!lane) (tensor ? cmB : cmA)[gc] = cs * (1.f / 4096.f);
    }
}

// ------------------------- per-position mean-sub + L2 normalize -> bf16 hi/lo, position-major
__global__ void posnorm_split(const float* __restrict__ fa, const float* __restrict__ fb,
                              const float* __restrict__ cmA, const float* __restrict__ cmB,
                              __nv_bfloat16* __restrict__ axh, __nv_bfloat16* __restrict__ axl,
                              __nv_bfloat16* __restrict__ bxh, __nv_bfloat16* __restrict__ bxl) {
    int idx = blockIdx.x * 128 + threadIdx.x;        // 0..16383
    int tensor = idx >> 13, sub = idx & 8191;
    int n = sub >> 12, pq = sub & 4095;
    const float* z  = (tensor ? fb : fa) + (size_t)n * 64 * 4096 + pq;
    const float* cm = (tensor ? cmB : cmA) + n * 64;
    float ss = 0.f;
    #pragma unroll
    for (int c = 0; c < 64; c++) { float v = z[(size_t)c * 4096] - cm[c]; ss += v * v; }
    float inv = 1.f / (sqrtf(ss) + EPSV);
    __nv_bfloat16* oh = (tensor ? bxh : axh) + ((size_t)n * 4096 + pq) * 64;
    __nv_bfloat16* ol = (tensor ? bxl : axl) + ((size_t)n * 4096 + pq) * 64;
    uint32_t uh[32], ul[32];
    #pragma unroll
    for (int c2 = 0; c2 < 32; c2++) {
        float v0 = (z[(size_t)(2*c2) * 4096]   - cm[2*c2])   * inv;
        float v1 = (z[(size_t)(2*c2+1) * 4096] - cm[2*c2+1]) * inv;
        __nv_bfloat162 h2, l2;
        h2.x = __float2bfloat16(v0); h2.y = __float2bfloat16(v1);
        l2.x = __float2bfloat16(v0 - __bfloat162float(h2.x));
        l2.y = __float2bfloat16(v1 - __bfloat162float(h2.y));
        uh[c2] = *reinterpret_cast<uint32_t*>(&h2);
        ul[c2] = *reinterpret_cast<uint32_t*>(&l2);
    }
    #pragma unroll
    for (int j = 0; j < 8; j++) {
        *reinterpret_cast<uint4*>(oh + j * 8) = *reinterpret_cast<uint4*>(&uh[j * 4]);
        *reinterpret_cast<uint4*>(ol + j * 8) = *reinterpret_cast<uint4*>(&ul[j * 4]);
    }
}

// ------------------------- generic 3x3 conv stage (3ch->3ch) + fused stat partials
__global__ void stage_conv(const float* __restrict__ in, const float2* __restrict__ instat,
                           int npart_in, int use_norm,
                           const float* __restrict__ W, const float* __restrict__ bias,
                           float* __restrict__ outraw, float2* __restrict__ pstat,
                           int H, int Wi, int Ho, int Wo, int stride, int reflect) {
    int planeSz = Ho * Wo;
    int bpp = planeSz >> 8;
    int plane = blockIdx.x / bpp;
    int n = plane / 3, co = plane % 3;
    int tid = threadIdx.x, lane = tid & 31, w = tid >> 5;
    __shared__ float s_m[3], s_inv[3], shA[8], shB[8];
    if (use_norm && w < 3) {
        float s = 0.f, s2 = 0.f;
        for (int t = lane; t < npart_in; t += 32) {
            float2 v = instat[(n * 3 + w) * npart_in + t]; s += v.x; s2 += v.y;
        }
        #pragma unroll
        for (int o = 16; o; o >>= 1) { s += __shfl_down_sync(~0u, s, o); s2 += __shfl_down_sync(~0u, s2, o); }
        if (!lane) {
            float Lf = (float)(H * Wi);
            float m = s / Lf; float var = fmaxf(s2 / Lf - m * m, 0.f);
            s_m[w] = m; s_inv[w] = rsqrtf(var + EPSV);
        }
    }
    if (use_norm) __syncthreads();
    float mm[3], ii[3];
    if (use_norm) { mm[0]=s_m[0]; mm[1]=s_m[1]; mm[2]=s_m[2]; ii[0]=s_inv[0]; ii[1]=s_inv[1]; ii[2]=s_inv[2]; }

    int opix = (blockIdx.x % bpp) * 256 + tid;
    int ho = opix / Wo, wo = opix % Wo;
    float acc = bias[co];
    const float* inb = in + (size_t)n * 3 * H * Wi;
    #pragma unroll
    for (int ci = 0; ci < 3; ci++) {
        const float* ip = inb + (size_t)ci * H * Wi;
        #pragma unroll
        for (int kh = 0; kh < 3; kh++) {
            int hi = ho * stride + kh - 1;
            if (reflect) { hi = hi < 0 ? -hi : (hi >= H ? 2 * H - 2 - hi : hi); }
            else if (hi < 0 || hi >= H) continue;
            #pragma unroll
            for (int kw = 0; kw < 3; kw++) {
                int wv = wo * stride + kw - 1;
                if (reflect) { wv = wv < 0 ? -wv : (wv >= Wi ? 2 * Wi - 2 - wv : wv); }
                else if (wv < 0 || wv >= Wi) continue;
                float v = ip[(size_t)hi * Wi + wv];
                if (use_norm) { v = (v - mm[ci]) * ii[ci]; v = v >= 0.f ? v : 0.2f * v; }
                acc = fmaf(v, W[((co * 3 + ci) * 3 + kh) * 3 + kw], acc);
            }
        }
    }
    outraw[(size_t)plane * planeSz + opix] = acc;

    float s = acc, s2 = acc * acc;
    #pragma unroll
    for (int o = 16; o; o >>= 1) { s += __shfl_down_sync(~0u, s, o); s2 += __shfl_down_sync(~0u, s2, o); }
    if (!lane) { shA[w] = s; shB[w] = s2; }
    __syncthreads();
    if (w == 0) {
        s  = (lane < 8) ? shA[lane] : 0.f;
        s2 = (lane < 8) ? shB[lane] : 0.f;
        #pragma unroll
        for (int o = 4; o; o >>= 1) { s += __shfl_down_sync(~0u, s, o); s2 += __shfl_down_sync(~0u, s2, o); }
        if (!lane) pstat[plane * bpp + (blockIdx.x % bpp)] = make_float2(s, s2);
    }
}

// ------------------------- bilinear 2x upsample (align_corners), optional norm+leaky on load
__global__ void up2x_k(const float* __restrict__ in, const float2* __restrict__ instat,
                       int npart_in, int use_norm, float* __restrict__ out, int S) {
    int O = 2 * S;
    int planeSz = O * O;
    int bpp = planeSz >> 8;
    int plane = blockIdx.x / bpp;
    int tid = threadIdx.x, lane = tid & 31, w = tid >> 5;
    __shared__ float sh_m, sh_inv;
    if (use_norm && w == 0) {
        float s = 0.f, s2 = 0.f;
        for (int t = lane; t < npart_in; t += 32) {
            float2 v = instat[plane * npart_in + t]; s += v.x; s2 += v.y;
        }
        #pragma unroll
        for (int o = 16; o; o >>= 1) { s += __shfl_down_sync(~0u, s, o); s2 += __shfl_down_sync(~0u, s2, o); }
        if (!lane) {
            float Lf = (float)(S * S);
            float m = s / Lf; float var = fmaxf(s2 / Lf - m * m, 0.f);
            sh_m = m; sh_inv = rsqrtf(var + EPSV);
        }
    }
    if (use_norm) __syncthreads();
    float m = use_norm ? sh_m : 0.f, inv = use_norm ? sh_inv : 1.f;

    int opix = (blockIdx.x % bpp) * 256 + tid;
    int ho = opix / O, wo = opix % O;
    float r = (float)(S - 1) / (float)(O - 1);
    float ph = ho * r, pw = wo * r;
    int h0 = (int)floorf(ph), w0 = (int)floorf(pw);
    float fh = ph - h0, fw = pw - w0;
    int h1 = min(h0 + 1, S - 1), w1 = min(w0 + 1, S - 1);
    const float* ib = in + (size_t)plane * S * S;
    float v00 = ib[h0 * S + w0], v10 = ib[h1 * S + w0], v01 = ib[h0 * S + w1], v11 = ib[h1 * S + w1];
    if (use_norm) {
        v00 = (v00 - m) * inv; v00 = v00 >= 0.f ? v00 : 0.2f * v00;
        v10 = (v10 - m) * inv; v10 = v10 >= 0.f ? v10 : 0.2f * v10;
        v01 = (v01 - m) * inv; v01 = v01 >= 0.f ? v01 : 0.2f * v01;
        v11 = (v11 - m) * inv; v11 = v11 >= 0.f ? v11 : 0.2f * v11;
    }
    float v = v00 * (1.f - fh) * (1.f - fw) + v10 * fh * (1.f - fw)
            + v01 * (1.f - fh) * fw + v11 * fh * fw;
    out[(size_t)plane * planeSz + opix] = v;
}

// ------------------------- final IN + leaky -> d_out
__global__ void final_apply(const float* __restrict__ raw, const float2* __restrict__ ps,
                            float* __restrict__ out) {
    int plane = blockIdx.x >> 8;
    int tid = threadIdx.x, lane = tid & 31, w = tid >> 5;
    __shared__ float shA[8], shB[8], sh_m, sh_inv;
    float2 v2 = ps[plane * 256 + tid];
    float s = v2.x, s2 = v2.y;
    #pragma unroll
    for (int o = 16; o; o >>= 1) { s += __shfl_down_sync(~0u, s, o); s2 += __shfl_down_sync(~0u, s2, o); }
    if (!lane) { shA[w] = s; shB[w] = s2; }
    __syncthreads();
    if (w == 0) {
        s  = (lane < 8) ? shA[lane] : 0.f;
        s2 = (lane < 8) ? shB[lane] : 0.f;
        #pragma unroll
        for (int o = 4; o; o >>= 1) { s += __shfl_down_sync(~0u, s, o); s2 += __shfl_down_sync(~0u, s2, o); }
        if (!lane) {
            float m = s * (1.f / 65536.f);
            float var = fmaxf(s2 * (1.f / 65536.f) - m * m, 0.f);
            sh_m = m; sh_inv = rsqrtf(var + EPSV);
        }
    }
    __syncthreads();
    int idx = blockIdx.x * 256 + tid;
    float x = (raw[idx] - sh_m) * sh_inv;
    out[idx] = x >= 0.f ? x : 0.2f * x;
}

// ------------------------- energy via HMMA (mma.sync bf16 hi/lo, 4 regions = full product)
// D = (Ah+Al).(Bh+Bl); E' = exp(100*D - 50) -> gmem; column partials of sum(E') and fc sums.
// dyn smem: tiles [0,64KB): Ah,Al,Bh,Bl each 16KB SW128; fcs @65536 (1536B); red aliases tile0.
__global__ void __launch_bounds__(256, 2)
energy_mma(const __nv_bfloat16* __restrict__ axh, const __nv_bfloat16* __restrict__ axl,
           const __nv_bfloat16* __restrict__ bxh, const __nv_bfloat16* __restrict__ bxl,
           const float* __restrict__ fc2raw, const float2* __restrict__ ps2,
           float* __restrict__ E, float* __restrict__ spart, float* __restrict__ apart) {
    extern __shared__ char smem[];
    uint32_t sb = smem_u32(smem);
    float*  fcs = (float*)(smem + 65536);
    float4* red = (float4*)smem;            // aliases tiles (used after mainloop)
    __shared__ float s_m[3], s_inv[3];

    int tid = threadIdx.x, wid = tid >> 5, lane = tid & 31;
    int wm = wid & 3, wn = wid >> 2;
    int n = blockIdx.z, q0 = blockIdx.x * 128, p0 = blockIdx.y * 128, pb = blockIdx.y;

    // fc2 IN stats (redundant reduce of 16 partials)
    if (wid < 3) {
        float s = 0.f, s2 = 0.f;
        if (lane < 16) { float2 v = ps2[(n * 3 + wid) * 16 + lane]; s = v.x; s2 = v.y; }
        #pragma unroll
        for (int o = 16; o; o >>= 1) { s += __shfl_down_sync(~0u, s, o); s2 += __shfl_down_sync(~0u, s2, o); }
        if (!lane) {
            float m = s * (1.f / 4096.f);
            float var = fmaxf(s2 * (1.f / 4096.f) - m * m, 0.f);
            s_m[wid] = m; s_inv[wid] = rsqrtf(var + EPSV);
        }
    }
    // tile loads: 0=Ah(fb hi rows p), 1=Al(fb lo), 2=Bh(fa hi rows q), 3=Bl(fa lo); SW128, 128B rows
    {
        const __nv_bfloat16* srcs[4] = { bxh, bxl, axh, axl };
        #pragma unroll
        for (int r = 0; r < 4; r++) {
            int rowbase = (r < 2) ? p0 : q0;
            const char* src = (const char*)(srcs[r] + ((size_t)n * 4096 + rowbase) * 64);
            char* dst = smem + r * 16384;
            #pragma unroll
            for (int it = 0; it < 4; it++) {
                uint32_t off = tid * 16 + it * 4096;
                *reinterpret_cast<uint4*>(dst + sw128(off)) = *reinterpret_cast<const uint4*>(src + off);
            }
        }
    }
    __syncthreads();
    // normalized fc tile (p rows of this block)
    for (int t = tid; t < 384; t += 256) {
        int c = t >> 7, i = t & 127;
        float v = fc2raw[((size_t)n * 3 + c) * 4096 + p0 + i];
        v = (v - s_m[c]) * s_inv[c];
        fcs[c * 128 + i] = v >= 0.f ? v : 0.2f * v;
    }
    __syncthreads();

    // ---- mainloop: 4 regions x 4 k16-steps, warp tile 32x64
    float acc[2][8][4] = {};
    int lane15 = lane & 15, lanehi = (lane >> 4) * 16;
    uint32_t tA[2] = { sb, sb + 16384 };            // Ah, Al
    uint32_t tB[2] = { sb + 32768, sb + 49152 };    // Bh, Bl
    #pragma unroll
    for (int reg_ = 0; reg_ < 4; reg_++) {
        uint32_t Abase = tA[reg_ >> 1];
        uint32_t Bbase = tB[reg_ & 1];
        #pragma unroll
        for (int ks = 0; ks < 4; ks++) {
            int kb = ks * 32;
            uint32_t a[2][4];
            #pragma unroll
            for (int mb = 0; mb < 2; mb++) {
                int row = wm * 32 + mb * 16 + lane15;
                ldsm_x4(a[mb], Abase + sw128(row * 128 + kb + lanehi));
            }
            uint32_t b[8][2];
            #pragma unroll
            for (int nb2 = 0; nb2 < 4; nb2++) {
                int row = wn * 64 + nb2 * 16 + lane15;
                uint32_t r4[4];
                ldsm_x4(r4, Bbase + sw128(row * 128 + kb + lanehi));
                b[2*nb2][0]   = r4[0]; b[2*nb2][1]   = r4[2];
                b[2*nb2+1][0] = r4[1]; b[2*nb2+1][1] = r4[3];
            }
            #pragma unroll
            for (int mb = 0; mb < 2; mb++)
                #pragma unroll
                for (int nb = 0; nb < 8; nb++)
                    mma16816(acc[mb][nb], a[mb], b[nb]);
        }
    }
    __syncthreads();   // tiles no longer needed; red may alias

    // ---- epilogue: exp, store E', per-column partials
    // fragment rows: k=mb*2+h -> row = wm*32 + mb*16 + h*8 + lane/4
    float* Eb = E + (size_t)n * 4096 * 4096;
    int rq = lane >> 2;           // row offset within 8
    int cq = 2 * (lane & 3);      // col pair within n8
    float fcv[3][4];
    #pragma unroll
    for (int k = 0; k < 4; k++) {
        int r = wm * 32 + (k >> 1) * 16 + (k & 1) * 8 + rq;
        fcv[0][k] = fcs[r]; fcv[1][k] = fcs[128 + r]; fcv[2][k] = fcs[256 + r];
    }
    #pragma unroll
    for (int nb = 0; nb < 8; nb++) {
        float s[2] = {}, A0[2] = {}, A1[2] = {}, A2[2] = {};
        #pragma unroll
        for (int k = 0; k < 4; k++) {
            int mb = k >> 1, h = k & 1;
            float e0 = __expf(fmaf(100.f, acc[mb][nb][h*2+0], -50.f));
            float e1 = __expf(fmaf(100.f, acc[mb][nb][h*2+1], -50.f));
            int prow = p0 + wm * 32 + mb * 16 + h * 8 + rq;
            int qcol = q0 + wn * 64 + nb * 8 + cq;
            *reinterpret_cast<float2*>(Eb + (size_t)prow * 4096 + qcol) = make_float2(e0, e1);
            s[0] += e0; s[1] += e1;
            A0[0] = fmaf(fcv[0][k], e0, A0[0]); A0[1] = fmaf(fcv[0][k], e1, A0[1]);
            A1[0] = fmaf(fcv[1][k], e0, A1[0]); A1[1] = fmaf(fcv[1][k], e1, A1[1]);
            A2[0] = fmaf(fcv[2][k], e0, A2[0]); A2[1] = fmaf(fcv[2][k], e1, A2[1]);
        }
        // reduce over the 8 row-lanes (same lane&3): xor masks 4, 8, 16
        #pragma unroll
        for (int msk = 4; msk <= 16; msk <<= 1) {
            #pragma unroll
            for (int u = 0; u < 2; u++) {
                s[u]  += __shfl_xor_sync(~0u, s[u],  msk);
                A0[u] += __shfl_xor_sync(~0u, A0[u], msk);
                A1[u] += __shfl_xor_sync(~0u, A1[u], msk);
                A2[u] += __shfl_xor_sync(~0u, A2[u], msk);
            }
        }
        if (lane < 4) {
            int col = wn * 64 + nb * 8 + 2 * lane;
            red[(col    ) * 4 + wm] = make_float4(s[0], A0[0], A1[0], A2[0]);
            red[(col + 1) * 4 + wm] = make_float4(s[1], A0[1], A1[1], A2[1]);
        }
    }
    __syncthreads();
    if (tid < 128) {
        float4 r0 = red[tid*4+0], r1 = red[tid*4+1], r2 = red[tid*4+2], r3 = red[tid*4+3];
        size_t base = (size_t)(n * 32) + pb;
        int q = q0 + tid;
        spart[base * 4096 + q]           = r0.x + r1.x + r2.x + r3.x;
        apart[(base * 3 + 0) * 4096 + q] = r0.y + r1.y + r2.y + r3.y;
        apart[(base * 3 + 1) * 4096 + q] = r0.z + r1.z + r2.z + r3.z;
        apart[(base * 3 + 2) * 4096 + q] = r0.w + r1.w + r2.w + r3.w;
    }
}

// ------------------------- reduce partials -> 1/sum and fc_warp
__global__ void colsum_final(const float* __restrict__ spart, const float* __restrict__ apart,
                             float* __restrict__ srecip, float* __restrict__ fcw) {
    int idx = blockIdx.x * 256 + threadIdx.x;
    int n = idx >> 12, q = idx & 4095;
    float s = 0.f, a0 = 0.f, a1 = 0.f, a2 = 0.f;
    for (int pb = 0; pb < 32; pb++) {
        size_t base = (size_t)(n * 32) + pb;
        s  += spart[base * 4096 + q];
        a0 += apart[(base * 3 + 0) * 4096 + q];
        a1 += apart[(base * 3 + 1) * 4096 + q];
        a2 += apart[(base * 3 + 2) * 4096 + q];
    }
    float inv = 1.f / s;
    srecip[idx] = inv;
    fcw[((size_t)n * 3 + 0) * 4096 + q] = a0 * inv;
    fcw[((size_t)n * 3 + 1) * 4096 + q] = a1 * inv;
    fcw[((size_t)n * 3 + 2) * 4096 + q] = a2 * inv;
}

// ------------------------- scale E' by 1/sum -> corr (in place)
__global__ void scale_kernel(float* __restrict__ E, const float* __restrict__ srecip) {
    size_t i4 = (size_t)blockIdx.x * blockDim.x + threadIdx.x;
    size_t idx = i4 * 4;
    int n = (int)(i4 >> 22);
    int q = (int)(idx & 4095);
    float4 e = *reinterpret_cast<float4*>(E + idx);
    float4 sv = *reinterpret_cast<const float4*>(srecip + n * 4096 + q);
    e.x *= sv.x; e.y *= sv.y; e.z *= sv.z; e.w *= sv.w;
    *reinterpret_cast<float4*>(E + idx) = e;
}

// ------------------------- launch -------------------------
extern "C" void kernel_launch(void* const* d_in, const int* in_sizes, int n_in,
                              void* d_out, int out_size) {
    const float* fa_raw = (const float*)d_in[0];
    const float* fb_raw = (const float*)d_in[1];
    const float* fc_raw = (const float*)d_in[2];
    const float* Wa = (const float*)d_in[3];   const float* ba = (const float*)d_in[4];
    const float* Wb = (const float*)d_in[5];   const float* bb = (const float*)d_in[6];
    const float* Wc1 = (const float*)d_in[7];  const float* bc1 = (const float*)d_in[8];
    const float* Wc2 = (const float*)d_in[9];  const float* bc2 = (const float*)d_in[10];
    const float* Wu1 = (const float*)d_in[11]; const float* bu1 = (const float*)d_in[12];
    const float* Wu2 = (const float*)d_in[13]; const float* bu2 = (const float*)d_in[14];
    float* out  = (float*)d_out;
    float* corr = out + 2 * 3 * 256 * 256;

    float *p_fa, *p_fb, *p_cmA, *p_cmB;
    float *p_fc1raw, *p_fc2raw, *p_fcw, *p_up1, *p_cv1raw, *p_up2, *p_cv2raw;
    float *p_spart, *p_apart, *p_srecip;
    float2 *p_psA, *p_psB, *p_ps1, *p_ps2, *p_ps3, *p_ps4;
    __nv_bfloat16 *p_axh, *p_axl, *p_bxh, *p_bxl;
    cudaGetSymbolAddress((void**)&p_fa, g_fa);       cudaGetSymbolAddress((void**)&p_fb, g_fb);
    cudaGetSymbolAddress((void**)&p_psA, g_psA);     cudaGetSymbolAddress((void**)&p_psB, g_psB);
    cudaGetSymbolAddress((void**)&p_cmA, g_cmA);     cudaGetSymbolAddress((void**)&p_cmB, g_cmB);
    cudaGetSymbolAddress((void**)&p_axh, g_axh);     cudaGetSymbolAddress((void**)&p_axl, g_axl);
    cudaGetSymbolAddress((void**)&p_bxh, g_bxh);     cudaGetSymbolAddress((void**)&p_bxl, g_bxl);
    cudaGetSymbolAddress((void**)&p_fc1raw, g_fc1raw); cudaGetSymbolAddress((void**)&p_fc2raw, g_fc2raw);
    cudaGetSymbolAddress((void**)&p_ps1, g_ps1);     cudaGetSymbolAddress((void**)&p_ps2, g_ps2);
    cudaGetSymbolAddress((void**)&p_ps3, g_ps3);     cudaGetSymbolAddress((void**)&p_ps4, g_ps4);
    cudaGetSymbolAddress((void**)&p_fcw, g_fcw);     cudaGetSymbolAddress((void**)&p_up1, g_up1);
    cudaGetSymbolAddress((void**)&p_cv1raw, g_cv1raw); cudaGetSymbolAddress((void**)&p_up2, g_up2);
    cudaGetSymbolAddress((void**)&p_cv2raw, g_cv2raw);
    cudaGetSymbolAddress((void**)&p_spart, g_spart); cudaGetSymbolAddress((void**)&p_apart, g_apart);
    cudaGetSymbolAddress((void**)&p_srecip, g_srecip);

    // fa/fb feature path
    conv1x1_kernel<<<dim3(64, 2), 256>>>(fa_raw, Wa, ba, p_fa, p_psA);
    conv1x1_kernel<<<dim3(64, 2), 256>>>(fb_raw, Wb, bb, p_fb, p_psB);
    apply_sum_both<<<256, 256>>>(p_fa, p_fb, p_psA, p_psB, p_cmA, p_cmB);
    posnorm_split<<<128, 128>>>(p_fa, p_fb, p_cmA, p_cmB, p_axh, p_axl, p_bxh, p_bxl);

    // fc path
    stage_conv<<<384, 256>>>(fc_raw, nullptr, 0, 0, Wc1, bc1, p_fc1raw, p_ps1,
                             256, 256, 128, 128, 2, 1);
    stage_conv<<<96, 256>>>(p_fc1raw, p_ps1, 64, 1, Wc2, bc2, p_fc2raw, p_ps2,
                            128, 128, 64, 64, 2, 1);

    // correlation: HMMA GEMM + exp + partials; reduce; scale
    cudaFuncSetAttribute(energy_mma, cudaFuncAttributeMaxDynamicSharedMemorySize, 67200);
    energy_mma<<<dim3(32, 32, 2), 256, 67200>>>(p_axh, p_axl, p_bxh, p_bxl,
                                                p_fc2raw, p_ps2, corr, p_spart, p_apart);
    colsum_final<<<32, 256>>>(p_spart, p_apart, p_srecip, p_fcw);
    scale_kernel<<<32768, 256>>>(corr, p_srecip);

    // upsample block 1: 64 -> 128
    up2x_k<<<384, 256>>>(p_fcw, nullptr, 0, 0, p_up1, 64);
    stage_conv<<<384, 256>>>(p_up1, nullptr, 0, 0, Wu1, bu1, p_cv1raw, p_ps3,
                             128, 128, 128, 128, 1, 0);
    // upsample block 2: 128 -> 256 (norm+leaky of cv1 fused into upsample load)
    up2x_k<<<1536, 256>>>(p_cv1raw, p_ps3, 64, 1, p_up2, 128);
    stage_conv<<<1536, 256>>>(p_up2, nullptr, 0, 0, Wu2, bu2, p_cv2raw, p_ps4,
                              256, 256, 256, 256, 1, 0);
    final_apply<<<1536, 256>>>(p_cv2raw, p_ps4, out);
}

// round 11
// speedup vs baseline: 1.8197x; 1.0918x over previous
#include <cuda_runtime.h>
#include <cuda_bf16.h>
#include <math.h>
#include <stdint.h>

#define EPSV 1e-5f
typedef unsigned long long u64;

// ------------------------- scratch (device globals) -------------------------
__device__ __align__(16) float  g_fa [2*64*4096];
__device__ __align__(16) float  g_fb [2*64*4096];
__device__ __align__(16) float2 g_psA[2*64*64];
__device__ __align__(16) float2 g_psB[2*64*64];
__device__ __align__(16) float  g_cmA[128], g_cmB[128];
__device__ __align__(16) __nv_bfloat16 g_axh[2*4096*64];
__device__ __align__(16) __nv_bfloat16 g_axl[2*4096*64];
__device__ __align__(16) __nv_bfloat16 g_bxh[2*4096*64];
__device__ __align__(16) __nv_bfloat16 g_bxl[2*4096*64];
__device__ __align__(16) float  g_fc1raw[2*3*128*128];
__device__ __align__(16) float  g_fc2raw[2*3*64*64];
__device__ __align__(16) float2 g_ps1[6*64];
__device__ __align__(16) float2 g_ps2[6*16];
__device__ __align__(16) float2 g_ps3[6*64];
__device__ __align__(16) float2 g_ps4[6*256];
__device__ __align__(16) float  g_fcw[2*3*64*64];
__device__ __align__(16) float  g_up1[2*3*128*128];
__device__ __align__(16) float  g_cv1raw[2*3*128*128];
__device__ __align__(16) float  g_up2[2*3*256*256];
__device__ __align__(16) float  g_cv2raw[2*3*256*256];
__device__ __align__(16) float  g_spart[2*32*4096];
__device__ __align__(16) float  g_apart[2*32*3*4096];
__device__ __align__(16) float  g_srecip[2*4096];

// ------------------------- helpers -------------------------
__device__ __forceinline__ uint32_t smem_u32(const void* p) {
    uint32_t a;
    asm("{ .reg .u64 t; cvta.to.shared.u64 t, %1; cvt.u32.u64 %0, t; }" : "=r"(a) : "l"(p));
    return a;
}
static __device__ __forceinline__ uint32_t sw128(uint32_t o) { return o ^ ((o >> 3) & 0x70); }

__device__ __forceinline__ void ldsm_x4(uint32_t* r, uint32_t addr) {
    asm volatile("ldmatrix.sync.aligned.m8n8.x4.shared.b16 {%0,%1,%2,%3}, [%4];"
                 : "=r"(r[0]), "=r"(r[1]), "=r"(r[2]), "=r"(r[3]) : "r"(addr));
}
__device__ __forceinline__ void mma16816(float* d, const uint32_t* a, const uint32_t* b) {
    asm volatile("mma.sync.aligned.m16n8k16.row.col.f32.bf16.bf16.f32 "
                 "{%0,%1,%2,%3}, {%4,%5,%6,%7}, {%8,%9}, {%0,%1,%2,%3};"
                 : "+f"(d[0]), "+f"(d[1]), "+f"(d[2]), "+f"(d[3])
                 : "r"(a[0]), "r"(a[1]), "r"(a[2]), "r"(a[3]), "r"(b[0]), "r"(b[1]));
}

// ------------------------- device: 1x1 conv GEMM + IN-stat partials (one q-block, one tensor)
__device__ void dev_conv1x1(int bx, int n, const float* __restrict__ X, const float* __restrict__ W,
                            const float* __restrict__ bias, float* __restrict__ Y,
                            float2* __restrict__ pstat) {
    int q0 = bx * 64;
    __shared__ float Xs[64][64];
    __shared__ float Ws[64][65];
    int tx = threadIdx.x & 15, ty = threadIdx.x >> 4;
    float acc[4][4] = {};
    const float* Xb = X + (size_t)n * 256 * 4096;

    for (int k0 = 0; k0 < 256; k0 += 64) {
        int r  = threadIdx.x >> 4;
        int c4 = threadIdx.x & 15;
        #pragma unroll
        for (int rr = 0; rr < 64; rr += 16) {
            float4 v = *reinterpret_cast<const float4*>(Xb + (size_t)(k0 + r + rr) * 4096 + q0 + c4 * 4);
            *reinterpret_cast<float4*>(&Xs[r + rr][c4 * 4]) = v;
            int co = r + rr;
            float4 w = *reinterpret_cast<const float4*>(W + co * 256 + k0 + c4 * 4);
            Ws[c4*4+0][co] = w.x; Ws[c4*4+1][co] = w.y; Ws[c4*4+2][co] = w.z; Ws[c4*4+3][co] = w.w;
        }
        __syncthreads();
        #pragma unroll
        for (int k = 0; k < 64; k++) {
            float a[4];
            *reinterpret_cast<float4*>(a) = *reinterpret_cast<float4*>(&Xs[k][tx * 4]);
            float b0 = Ws[k][ty*4+0], b1 = Ws[k][ty*4+1], b2 = Ws[k][ty*4+2], b3 = Ws[k][ty*4+3];
            #pragma unroll
            for (int j = 0; j < 4; j++) {
                acc[0][j] = fmaf(b0, a[j], acc[0][j]);
                acc[1][j] = fmaf(b1, a[j], acc[1][j]);
                acc[2][j] = fmaf(b2, a[j], acc[2][j]);
                acc[3][j] = fmaf(b3, a[j], acc[3][j]);
            }
        }
        __syncthreads();
    }
    float* Yb = Y + (size_t)n * 64 * 4096;
    float ls[4], ls2[4];
    #pragma unroll
    for (int i = 0; i < 4; i++) {
        int co = ty * 4 + i;
        float bv = bias[co];
        float o0 = acc[i][0] + bv, o1 = acc[i][1] + bv, o2 = acc[i][2] + bv, o3 = acc[i][3] + bv;
        float4 o = { o0, o1, o2, o3 };
        *reinterpret_cast<float4*>(Yb + (size_t)co * 4096 + q0 + tx * 4) = o;
        ls[i]  = o0 + o1 + o2 + o3;
        ls2[i] = o0*o0 + o1*o1 + o2*o2 + o3*o3;
    }
    __syncthreads();
    float* redS  = &Xs[0][0];
    float* redS2 = redS + 1024;
    #pragma unroll
    for (int i = 0; i < 4; i++) {
        int co = ty * 4 + i;
        redS[co * 16 + tx]  = ls[i];
        redS2[co * 16 + tx] = ls2[i];
    }
    __syncthreads();
    if (threadIdx.x < 64) {
        float s = 0.f, s2 = 0.f;
        #pragma unroll
        for (int t = 0; t < 16; t++) { s += redS[threadIdx.x * 16 + t]; s2 += redS2[threadIdx.x * 16 + t]; }
        pstat[(n * 64 + threadIdx.x) * 64 + bx] = make_float2(s, s2);
    }
}

// ------------------------- device: fa/fb IN + leaky in place + channel-mean of result
__device__ void dev_apply_sum(int g, float* __restrict__ fa, float* __restrict__ fb,
                              const float2* __restrict__ psA, const float2* __restrict__ psB,
                              float* __restrict__ cmA, float* __restrict__ cmB) {
    int tensor = g >> 7, gc = g & 127;
    float* p = (tensor ? fb : fa) + (size_t)gc * 4096;
    const float2* ps = (tensor ? psB : psA) + gc * 64;
    __shared__ float sh_m, sh_inv, sh[8];
    int tid = threadIdx.x, lane = tid & 31, w = tid >> 5;
    if (w == 0) {
        float s = 0.f, s2 = 0.f;
        for (int t = lane; t < 64; t += 32) { float2 v = ps[t]; s += v.x; s2 += v.y; }
        #pragma unroll
        for (int o = 16; o; o >>= 1) { s += __shfl_down_sync(~0u, s, o); s2 += __shfl_down_sync(~0u, s2, o); }
        if (!lane) {
            float m = s * (1.f / 4096.f);
            float var = fmaxf(s2 * (1.f / 4096.f) - m * m, 0.f);
            sh_m = m; sh_inv = rsqrtf(var + EPSV);
        }
    }
    __syncthreads();
    float m = sh_m, inv = sh_inv, cs = 0.f;
    float4* p4 = (float4*)p;
    for (int i = tid; i < 1024; i += 256) {
        float4 v = p4[i];
        v.x = (v.x - m) * inv; v.x = v.x >= 0.f ? v.x : 0.2f * v.x;
        v.y = (v.y - m) * inv; v.y = v.y >= 0.f ? v.y : 0.2f * v.y;
        v.z = (v.z - m) * inv; v.z = v.z >= 0.f ? v.z : 0.2f * v.z;
        v.w = (v.w - m) * inv; v.w = v.w >= 0.f ? v.w : 0.2f * v.w;
        cs += v.x + v.y + v.z + v.w;
        p4[i] = v;
    }
    #pragma unroll
    for (int o = 16; o; o >>= 1) cs += __shfl_down_sync(~0u, cs, o);
    if (!lane) sh[w] = cs;
    __syncthreads();
    if (w == 0) {
        cs = (lane < 8) ? sh[lane] : 0.f;
        #pragma unroll
        for (int o = 4; o; o >>= 1) cs += __shfl_down_sync(~0u, cs, o);
        if (!lane) (tensor ? cmB : cmA)[gc] = cs * (1.f / 4096.f);
    }
}

// ------------------------- device: generic 3x3 conv stage + stat partials
__device__ void dev_stage_conv(int b, const float* __restrict__ in, const float2* __restrict__ instat,
                               int npart_in, int use_norm,
                               const float* __restrict__ W, const float* __restrict__ bias,
                               float* __restrict__ outraw, float2* __restrict__ pstat,
                               int H, int Wi, int Ho, int Wo, int stride, int reflect) {
    int planeSz = Ho * Wo;
    int bpp = planeSz >> 8;
    int plane = b / bpp;
    int n = plane / 3, co = plane % 3;
    int tid = threadIdx.x, lane = tid & 31, w = tid >> 5;
    __shared__ float s_m[3], s_inv[3], shA[8], shB[8];
    if (use_norm && w < 3) {
        float s = 0.f, s2 = 0.f;
        for (int t = lane; t < npart_in; t += 32) {
            float2 v = instat[(n * 3 + w) * npart_in + t]; s += v.x; s2 += v.y;
        }
        #pragma unroll
        for (int o = 16; o; o >>= 1) { s += __shfl_down_sync(~0u, s, o); s2 += __shfl_down_sync(~0u, s2, o); }
        if (!lane) {
            float Lf = (float)(H * Wi);
            float m = s / Lf; float var = fmaxf(s2 / Lf - m * m, 0.f);
            s_m[w] = m; s_inv[w] = rsqrtf(var + EPSV);
        }
    }
    if (use_norm) __syncthreads();
    float mm[3], ii[3];
    if (use_norm) { mm[0]=s_m[0]; mm[1]=s_m[1]; mm[2]=s_m[2]; ii[0]=s_inv[0]; ii[1]=s_inv[1]; ii[2]=s_inv[2]; }

    int opix = (b % bpp) * 256 + tid;
    int ho = opix / Wo, wo = opix % Wo;
    float acc = bias[co];
    const float* inb = in + (size_t)n * 3 * H * Wi;
    #pragma unroll
    for (int ci = 0; ci < 3; ci++) {
        const float* ip = inb + (size_t)ci * H * Wi;
        #pragma unroll
        for (int kh = 0; kh < 3; kh++) {
            int hi = ho * stride + kh - 1;
            if (reflect) { hi = hi < 0 ? -hi : (hi >= H ? 2 * H - 2 - hi : hi); }
            else if (hi < 0 || hi >= H) continue;
            #pragma unroll
            for (int kw = 0; kw < 3; kw++) {
                int wv = wo * stride + kw - 1;
                if (reflect) { wv = wv < 0 ? -wv : (wv >= Wi ? 2 * Wi - 2 - wv : wv); }
                else if (wv < 0 || wv >= Wi) continue;
                float v = ip[(size_t)hi * Wi + wv];
                if (use_norm) { v = (v - mm[ci]) * ii[ci]; v = v >= 0.f ? v : 0.2f * v; }
                acc = fmaf(v, W[((co * 3 + ci) * 3 + kh) * 3 + kw], acc);
            }
        }
    }
    outraw[(size_t)plane * planeSz + opix] = acc;

    float s = acc, s2 = acc * acc;
    #pragma unroll
    for (int o = 16; o; o >>= 1) { s += __shfl_down_sync(~0u, s, o); s2 += __shfl_down_sync(~0u, s2, o); }
    if (!lane) { shA[w] = s; shB[w] = s2; }
    __syncthreads();
    if (w == 0) {
        s  = (lane < 8) ? shA[lane] : 0.f;
        s2 = (lane < 8) ? shB[lane] : 0.f;
        #pragma unroll
        for (int o = 4; o; o >>= 1) { s += __shfl_down_sync(~0u, s, o); s2 += __shfl_down_sync(~0u, s2, o); }
        if (!lane) pstat[plane * bpp + (b % bpp)] = make_float2(s, s2);
    }
}

// ------------------------- device: bilinear 2x upsample, optional norm+leaky on load
__device__ void dev_up2x(int b, const float* __restrict__ in, const float2* __restrict__ instat,
                         int npart_in, int use_norm, float* __restrict__ out, int S) {
    int O = 2 * S;
    int planeSz = O * O;
    int bpp = planeSz >> 8;
    int plane = b / bpp;
    int tid = threadIdx.x, lane = tid & 31, w = tid >> 5;
    __shared__ float sh_m, sh_inv;
    if (use_norm && w == 0) {
        float s = 0.f, s2 = 0.f;
        for (int t = lane; t < npart_in; t += 32) {
            float2 v = instat[plane * npart_in + t]; s += v.x; s2 += v.y;
        }
        #pragma unroll
        for (int o = 16; o; o >>= 1) { s += __shfl_down_sync(~0u, s, o); s2 += __shfl_down_sync(~0u, s2, o); }
        if (!lane) {
            float Lf = (float)(S * S);
            float m = s / Lf; float var = fmaxf(s2 / Lf - m * m, 0.f);
            sh_m = m; sh_inv = rsqrtf(var + EPSV);
        }
    }
    if (use_norm) __syncthreads();
    float m = use_norm ? sh_m : 0.f, inv = use_norm ? sh_inv : 1.f;

    int opix = (b % bpp) * 256 + tid;
    int ho = opix / O, wo = opix % O;
    float r = (float)(S - 1) / (float)(O - 1);
    float ph = ho * r, pw = wo * r;
    int h0 = (int)floorf(ph), w0 = (int)floorf(pw);
    float fh = ph - h0, fw = pw - w0;
    int h1 = min(h0 + 1, S - 1), w1 = min(w0 + 1, S - 1);
    const float* ib = in + (size_t)plane * S * S;
    float v00 = ib[h0 * S + w0], v10 = ib[h1 * S + w0], v01 = ib[h0 * S + w1], v11 = ib[h1 * S + w1];
    if (use_norm) {
        v00 = (v00 - m) * inv; v00 = v00 >= 0.f ? v00 : 0.2f * v00;
        v10 = (v10 - m) * inv; v10 = v10 >= 0.f ? v10 : 0.2f * v10;
        v01 = (v01 - m) * inv; v01 = v01 >= 0.f ? v01 : 0.2f * v01;
        v11 = (v11 - m) * inv; v11 = v11 >= 0.f ? v11 : 0.2f * v11;
    }
    float v = v00 * (1.f - fh) * (1.f - fw) + v10 * fh * (1.f - fw)
            + v01 * (1.f - fh) * fw + v11 * fh * fw;
    out[(size_t)plane * planeSz + opix] = v;
}

// ------------------------- device: final IN + leaky -> d_out
__device__ void dev_final(int b, const float* __restrict__ raw, const float2* __restrict__ ps,
                          float* __restrict__ out) {
    int plane = b >> 8;
    int tid = threadIdx.x, lane = tid & 31, w = tid >> 5;
    __shared__ float shA[8], shB[8], sh_m, sh_inv;
    float2 v2 = ps[plane * 256 + tid];
    float s = v2.x, s2 = v2.y;
    #pragma unroll
    for (int o = 16; o; o >>= 1) { s += __shfl_down_sync(~0u, s, o); s2 += __shfl_down_sync(~0u, s2, o); }
    if (!lane) { shA[w] = s; shB[w] = s2; }
    __syncthreads();
    if (w == 0) {
        s  = (lane < 8) ? shA[lane] : 0.f;
        s2 = (lane < 8) ? shB[lane] : 0.f;
        #pragma unroll
        for (int o = 4; o; o >>= 1) { s += __shfl_down_sync(~0u, s, o); s2 += __shfl_down_sync(~0u, s2, o); }
        if (!lane) {
            float m = s * (1.f / 65536.f);
            float var = fmaxf(s2 * (1.f / 65536.f) - m * m, 0.f);
            sh_m = m; sh_inv = rsqrtf(var + EPSV);
        }
    }
    __syncthreads();
    int idx = b * 256 + tid;
    float x = (raw[idx] - sh_m) * sh_inv;
    out[idx] = x >= 0.f ? x : 0.2f * x;
}

// ------------------------- device: scale one 1024-element slice of E by 1/sum
__device__ void dev_scale(int gb, float* __restrict__ E, const float* __restrict__ srecip) {
    size_t i4 = (size_t)gb * 256 + threadIdx.x;
    size_t idx = i4 * 4;
    int n = (int)(i4 >> 22);
    int q = (int)(idx & 4095);
    float4 e = *reinterpret_cast<float4*>(E + idx);
    float4 sv = *reinterpret_cast<const float4*>(srecip + n * 4096 + q);
    e.x *= sv.x; e.y *= sv.y; e.z *= sv.z; e.w *= sv.w;
    *reinterpret_cast<float4*>(E + idx) = e;
}

// ------------------------- packed phase kernels -------------------------
// P1: conv1x1 for fa(128 blocks: n,qb) + fb(128) || fc conv1 (384)
__global__ void __launch_bounds__(256) phase1(
        const float* fa_raw, const float* fb_raw, const float* Wa, const float* ba,
        const float* Wb, const float* bb, float* fa, float* fb, float2* psA, float2* psB,
        const float* fc_raw, const float* Wc1, const float* bc1, float* fc1raw, float2* ps1) {
    int b = blockIdx.x;
    if (b < 256) {
        int t = b >> 7, n = (b >> 6) & 1, qb = b & 63;
        if (t == 0) dev_conv1x1(qb, n, fa_raw, Wa, ba, fa, psA);
        else        dev_conv1x1(qb, n, fb_raw, Wb, bb, fb, psB);
    } else {
        dev_stage_conv(b - 256, fc_raw, nullptr, 0, 0, Wc1, bc1, fc1raw, ps1,
                       256, 256, 128, 128, 2, 1);
    }
}

// P2: apply_sum_both (256) || fc conv2 (96)
__global__ void __launch_bounds__(256) phase2(
        float* fa, float* fb, const float2* psA, const float2* psB, float* cmA, float* cmB,
        const float* fc1raw, const float2* ps1, const float* Wc2, const float* bc2,
        float* fc2raw, float2* ps2) {
    int b = blockIdx.x;
    if (b < 256) dev_apply_sum(b, fa, fb, psA, psB, cmA, cmB);
    else dev_stage_conv(b - 256, fc1raw, ps1, 64, 1, Wc2, bc2, fc2raw, ps2,
                        128, 128, 64, 64, 2, 1);
}

// U-phases: upsample-chain part || scale slice
__global__ void __launch_bounds__(256) phaseU1(const float* fcw, float* up1,
                                               float* E, const float* srecip) {
    int b = blockIdx.x;
    if (b < 384) dev_up2x(b, fcw, nullptr, 0, 0, up1, 64);
    else dev_scale(b - 384 + 0, E, srecip);
}
__global__ void __launch_bounds__(256) phaseU2(const float* up1, const float* Wu1, const float* bu1,
                                               float* cv1raw, float2* ps3,
                                               float* E, const float* srecip) {
    int b = blockIdx.x;
    if (b < 384) dev_stage_conv(b, up1, nullptr, 0, 0, Wu1, bu1, cv1raw, ps3,
                                128, 128, 128, 128, 1, 0);
    else dev_scale(b - 384 + 6554, E, srecip);
}
__global__ void __launch_bounds__(256) phaseU3(const float* cv1raw, const float2* ps3, float* up2,
                                               float* E, const float* srecip) {
    int b = blockIdx.x;
    if (b < 1536) dev_up2x(b, cv1raw, ps3, 64, 1, up2, 128);
    else dev_scale(b - 1536 + 13108, E, srecip);
}
__global__ void __launch_bounds__(256) phaseU4(const float* up2, const float* Wu2, const float* bu2,
                                               float* cv2raw, float2* ps4,
                                               float* E, const float* srecip) {
    int b = blockIdx.x;
    if (b < 1536) dev_stage_conv(b, up2, nullptr, 0, 0, Wu2, bu2, cv2raw, ps4,
                                 256, 256, 256, 256, 1, 0);
    else dev_scale(b - 1536 + 19662, E, srecip);
}
__global__ void __launch_bounds__(256) phaseU5(const float* cv2raw, const float2* ps4, float* out,
                                               float* E, const float* srecip) {
    int b = blockIdx.x;
    if (b < 1536) dev_final(b, cv2raw, ps4, out);
    else dev_scale(b - 1536 + 26215, E, srecip);
}

// ------------------------- posnorm: mean-sub + L2 normalize -> bf16 hi/lo, position-major
__global__ void posnorm_split(const float* __restrict__ fa, const float* __restrict__ fb,
                              const float* __restrict__ cmA, const float* __restrict__ cmB,
                              __nv_bfloat16* __restrict__ axh, __nv_bfloat16* __restrict__ axl,
                              __nv_bfloat16* __restrict__ bxh, __nv_bfloat16* __restrict__ bxl) {
    int idx = blockIdx.x * 128 + threadIdx.x;        // 0..16383
    int tensor = idx >> 13, sub = idx & 8191;
    int n = sub >> 12, pq = sub & 4095;
    const float* z  = (tensor ? fb : fa) + (size_t)n * 64 * 4096 + pq;
    const float* cm = (tensor ? cmB : cmA) + n * 64;
    float ss = 0.f;
    #pragma unroll
    for (int c = 0; c < 64; c++) { float v = z[(size_t)c * 4096] - cm[c]; ss += v * v; }
    float inv = 1.f / (sqrtf(ss) + EPSV);
    __nv_bfloat16* oh = (tensor ? bxh : axh) + ((size_t)n * 4096 + pq) * 64;
    __nv_bfloat16* ol = (tensor ? bxl : axl) + ((size_t)n * 4096 + pq) * 64;
    uint32_t uh[32], ul[32];
    #pragma unroll
    for (int c2 = 0; c2 < 32; c2++) {
        float v0 = (z[(size_t)(2*c2) * 4096]   - cm[2*c2])   * inv;
        float v1 = (z[(size_t)(2*c2+1) * 4096] - cm[2*c2+1]) * inv;
        __nv_bfloat162 h2, l2;
        h2.x = __float2bfloat16(v0); h2.y = __float2bfloat16(v1);
        l2.x = __float2bfloat16(v0 - __bfloat162float(h2.x));
        l2.y = __float2bfloat16(v1 - __bfloat162float(h2.y));
        uh[c2] = *reinterpret_cast<uint32_t*>(&h2);
        ul[c2] = *reinterpret_cast<uint32_t*>(&l2);
    }
    #pragma unroll
    for (int j = 0; j < 8; j++) {
        *reinterpret_cast<uint4*>(oh + j * 8) = *reinterpret_cast<uint4*>(&uh[j * 4]);
        *reinterpret_cast<uint4*>(ol + j * 8) = *reinterpret_cast<uint4*>(&ul[j * 4]);
    }
}

// ------------------------- energy via HMMA (bf16 hi/lo, 4 regions = full product)
__global__ void __launch_bounds__(256, 2)
energy_mma(const __nv_bfloat16* __restrict__ axh, const __nv_bfloat16* __restrict__ axl,
           const __nv_bfloat16* __restrict__ bxh, const __nv_bfloat16* __restrict__ bxl,
           const float* __restrict__ fc2raw, const float2* __restrict__ ps2,
           float* __restrict__ E, float* __restrict__ spart, float* __restrict__ apart) {
    extern __shared__ char smem[];
    uint32_t sb = smem_u32(smem);
    float*  fcs = (float*)(smem + 65536);
    float4* red = (float4*)smem;            // aliases tiles (used after mainloop)
    __shared__ float s_m[3], s_inv[3];

    int tid = threadIdx.x, wid = tid >> 5, lane = tid & 31;
    int wm = wid & 3, wn = wid >> 2;
    int n = blockIdx.z, q0 = blockIdx.x * 128, p0 = blockIdx.y * 128, pb = blockIdx.y;

    if (wid < 3) {
        float s = 0.f, s2 = 0.f;
        if (lane < 16) { float2 v = ps2[(n * 3 + wid) * 16 + lane]; s = v.x; s2 = v.y; }
        #pragma unroll
        for (int o = 16; o; o >>= 1) { s += __shfl_down_sync(~0u, s, o); s2 += __shfl_down_sync(~0u, s2, o); }
        if (!lane) {
            float m = s * (1.f / 4096.f);
            float var = fmaxf(s2 * (1.f / 4096.f) - m * m, 0.f);
            s_m[wid] = m; s_inv[wid] = rsqrtf(var + EPSV);
        }
    }
    {
        const __nv_bfloat16* srcs[4] = { bxh, bxl, axh, axl };
        #pragma unroll
        for (int r = 0; r < 4; r++) {
            int rowbase = (r < 2) ? p0 : q0;
            const char* src = (const char*)(srcs[r] + ((size_t)n * 4096 + rowbase) * 64);
            char* dst = smem + r * 16384;
            #pragma unroll
            for (int it = 0; it < 4; it++) {
                uint32_t off = tid * 16 + it * 4096;
                *reinterpret_cast<uint4*>(dst + sw128(off)) = *reinterpret_cast<const uint4*>(src + off);
            }
        }
    }
    __syncthreads();
    for (int t = tid; t < 384; t += 256) {
        int c = t >> 7, i = t & 127;
        float v = fc2raw[((size_t)n * 3 + c) * 4096 + p0 + i];
        v = (v - s_m[c]) * s_inv[c];
        fcs[c * 128 + i] = v >= 0.f ? v : 0.2f * v;
    }
    __syncthreads();

    float acc[2][8][4] = {};
    int lane15 = lane & 15, lanehi = (lane >> 4) * 16;
    uint32_t tA[2] = { sb, sb + 16384 };
    uint32_t tB[2] = { sb + 32768, sb + 49152 };
    #pragma unroll
    for (int reg_ = 0; reg_ < 4; reg_++) {
        uint32_t Abase = tA[reg_ >> 1];
        uint32_t Bbase = tB[reg_ & 1];
        #pragma unroll
        for (int ks = 0; ks < 4; ks++) {
            int kb = ks * 32;
            uint32_t a[2][4];
            #pragma unroll
            for (int mb = 0; mb < 2; mb++) {
                int row = wm * 32 + mb * 16 + lane15;
                ldsm_x4(a[mb], Abase + sw128(row * 128 + kb + lanehi));
            }
            uint32_t b[8][2];
            #pragma unroll
            for (int nb2 = 0; nb2 < 4; nb2++) {
                int row = wn * 64 + nb2 * 16 + lane15;
                uint32_t r4[4];
                ldsm_x4(r4, Bbase + sw128(row * 128 + kb + lanehi));
                b[2*nb2][0]   = r4[0]; b[2*nb2][1]   = r4[2];
                b[2*nb2+1][0] = r4[1]; b[2*nb2+1][1] = r4[3];
            }
            #pragma unroll
            for (int mb = 0; mb < 2; mb++)
                #pragma unroll
                for (int nb = 0; nb < 8; nb++)
                    mma16816(acc[mb][nb], a[mb], b[nb]);
        }
    }
    __syncthreads();

    float* Eb = E + (size_t)n * 4096 * 4096;
    int rq = lane >> 2;
    int cq = 2 * (lane & 3);
    float fcv[3][4];
    #pragma unroll
    for (int k = 0; k < 4; k++) {
        int r = wm * 32 + (k >> 1) * 16 + (k & 1) * 8 + rq;
        fcv[0][k] = fcs[r]; fcv[1][k] = fcs[128 + r]; fcv[2][k] = fcs[256 + r];
    }
    #pragma unroll
    for (int nb = 0; nb < 8; nb++) {
        float s[2] = {}, A0[2] = {}, A1[2] = {}, A2[2] = {};
        #pragma unroll
        for (int k = 0; k < 4; k++) {
            int mb = k >> 1, h = k & 1;
            float e0 = __expf(fmaf(100.f, acc[mb][nb][h*2+0], -50.f));
            float e1 = __expf(fmaf(100.f, acc[mb][nb][h*2+1], -50.f));
            int prow = p0 + wm * 32 + mb * 16 + h * 8 + rq;
            int qcol = q0 + wn * 64 + nb * 8 + cq;
            *reinterpret_cast<float2*>(Eb + (size_t)prow * 4096 + qcol) = make_float2(e0, e1);
            s[0] += e0; s[1] += e1;
            A0[0] = fmaf(fcv[0][k], e0, A0[0]); A0[1] = fmaf(fcv[0][k], e1, A0[1]);
            A1[0] = fmaf(fcv[1][k], e0, A1[0]); A1[1] = fmaf(fcv[1][k], e1, A1[1]);
            A2[0] = fmaf(fcv[2][k], e0, A2[0]); A2[1] = fmaf(fcv[2][k], e1, A2[1]);
        }
        #pragma unroll
        for (int msk = 4; msk <= 16; msk <<= 1) {
            #pragma unroll
            for (int u = 0; u < 2; u++) {
                s[u]  += __shfl_xor_sync(~0u, s[u],  msk);
                A0[u] += __shfl_xor_sync(~0u, A0[u], msk);
                A1[u] += __shfl_xor_sync(~0u, A1[u], msk);
                A2[u] += __shfl_xor_sync(~0u, A2[u], msk);
            }
        }
        if (lane < 4) {
            int col = wn * 64 + nb * 8 + 2 * lane;
            red[(col    ) * 4 + wm] = make_float4(s[0], A0[0], A1[0], A2[0]);
            red[(col + 1) * 4 + wm] = make_float4(s[1], A0[1], A1[1], A2[1]);
        }
    }
    __syncthreads();
    if (tid < 128) {
        float4 r0 = red[tid*4+0], r1 = red[tid*4+1], r2 = red[tid*4+2], r3 = red[tid*4+3];
        size_t base = (size_t)(n * 32) + pb;
        int q = q0 + tid;
        spart[base * 4096 + q]           = r0.x + r1.x + r2.x + r3.x;
        apart[(base * 3 + 0) * 4096 + q] = r0.y + r1.y + r2.y + r3.y;
        apart[(base * 3 + 1) * 4096 + q] = r0.z + r1.z + r2.z + r3.z;
        apart[(base * 3 + 2) * 4096 + q] = r0.w + r1.w + r2.w + r3.w;
    }
}

// ------------------------- reduce partials -> 1/sum and fc_warp
__global__ void colsum_final(const float* __restrict__ spart, const float* __restrict__ apart,
                             float* __restrict__ srecip, float* __restrict__ fcw) {
    int idx = blockIdx.x * 256 + threadIdx.x;
    int n = idx >> 12, q = idx & 4095;
    float s = 0.f, a0 = 0.f, a1 = 0.f, a2 = 0.f;
    for (int pb = 0; pb < 32; pb++) {
        size_t base = (size_t)(n * 32) + pb;
        s  += spart[base * 4096 + q];
        a0 += apart[(base * 3 + 0) * 4096 + q];
        a1 += apart[(base * 3 + 1) * 4096 + q];
        a2 += apart[(base * 3 + 2) * 4096 + q];
    }
    float inv = 1.f / s;
    srecip[idx] = inv;
    fcw[((size_t)n * 3 + 0) * 4096 + q] = a0 * inv;
    fcw[((size_t)n * 3 + 1) * 4096 + q] = a1 * inv;
    fcw[((size_t)n * 3 + 2) * 4096 + q] = a2 * inv;
}

// ------------------------- launch -------------------------
extern "C" void kernel_launch(void* const* d_in, const int* in_sizes, int n_in,
                              void* d_out, int out_size) {
    const float* fa_raw = (const float*)d_in[0];
    const float* fb_raw = (const float*)d_in[1];
    const float* fc_raw = (const float*)d_in[2];
    const float* Wa = (const float*)d_in[3];   const float* ba = (const float*)d_in[4];
    const float* Wb = (const float*)d_in[5];   const float* bb = (const float*)d_in[6];
    const float* Wc1 = (const float*)d_in[7];  const float* bc1 = (const float*)d_in[8];
    const float* Wc2 = (const float*)d_in[9];  const float* bc2 = (const float*)d_in[10];
    const float* Wu1 = (const float*)d_in[11]; const float* bu1 = (const float*)d_in[12];
    const float* Wu2 = (const float*)d_in[13]; const float* bu2 = (const float*)d_in[14];
    float* out  = (float*)d_out;
    float* corr = out + 2 * 3 * 256 * 256;

    float *p_fa, *p_fb, *p_cmA, *p_cmB;
    float *p_fc1raw, *p_fc2raw, *p_fcw, *p_up1, *p_cv1raw, *p_up2, *p_cv2raw;
    float *p_spart, *p_apart, *p_srecip;
    float2 *p_psA, *p_psB, *p_ps1, *p_ps2, *p_ps3, *p_ps4;
    __nv_bfloat16 *p_axh, *p_axl, *p_bxh, *p_bxl;
    cudaGetSymbolAddress((void**)&p_fa, g_fa);       cudaGetSymbolAddress((void**)&p_fb, g_fb);
    cudaGetSymbolAddress((void**)&p_psA, g_psA);     cudaGetSymbolAddress((void**)&p_psB, g_psB);
    cudaGetSymbolAddress((void**)&p_cmA, g_cmA);     cudaGetSymbolAddress((void**)&p_cmB, g_cmB);
    cudaGetSymbolAddress((void**)&p_axh, g_axh);     cudaGetSymbolAddress((void**)&p_axl, g_axl);
    cudaGetSymbolAddress((void**)&p_bxh, g_bxh);     cudaGetSymbolAddress((void**)&p_bxl, g_bxl);
    cudaGetSymbolAddress((void**)&p_fc1raw, g_fc1raw); cudaGetSymbolAddress((void**)&p_fc2raw, g_fc2raw);
    cudaGetSymbolAddress((void**)&p_ps1, g_ps1);     cudaGetSymbolAddress((void**)&p_ps2, g_ps2);
    cudaGetSymbolAddress((void**)&p_ps3, g_ps3);     cudaGetSymbolAddress((void**)&p_ps4, g_ps4);
    cudaGetSymbolAddress((void**)&p_fcw, g_fcw);     cudaGetSymbolAddress((void**)&p_up1, g_up1);
    cudaGetSymbolAddress((void**)&p_cv1raw, g_cv1raw); cudaGetSymbolAddress((void**)&p_up2, g_up2);
    cudaGetSymbolAddress((void**)&p_cv2raw, g_cv2raw);
    cudaGetSymbolAddress((void**)&p_spart, g_spart); cudaGetSymbolAddress((void**)&p_apart, g_apart);
    cudaGetSymbolAddress((void**)&p_srecip, g_srecip);

    // P1: fa/fb 1x1 convs || fc conv1
    phase1<<<640, 256>>>(fa_raw, fb_raw, Wa, ba, Wb, bb, p_fa, p_fb, p_psA, p_psB,
                         fc_raw, Wc1, bc1, p_fc1raw, p_ps1);
    // P2: IN+leaky+chan-mean || fc conv2
    phase2<<<352, 256>>>(p_fa, p_fb, p_psA, p_psB, p_cmA, p_cmB,
                         p_fc1raw, p_ps1, Wc2, bc2, p_fc2raw, p_ps2);
    posnorm_split<<<128, 128>>>(p_fa, p_fb, p_cmA, p_cmB, p_axh, p_axl, p_bxh, p_bxl);

    // energy GEMM + exp + partials; reduce
    cudaFuncSetAttribute(energy_mma, cudaFuncAttributeMaxDynamicSharedMemorySize, 67200);
    energy_mma<<<dim3(32, 32, 2), 256, 67200>>>(p_axh, p_axl, p_bxh, p_bxl,
                                                p_fc2raw, p_ps2, corr, p_spart, p_apart);
    colsum_final<<<32, 256>>>(p_spart, p_apart, p_srecip, p_fcw);

    // U-phases: upsample chain packed with scale slices (5 x ~6554 blocks covers 32768)
    phaseU1<<<384 + 6554, 256>>>(p_fcw, p_up1, corr, p_srecip);
    phaseU2<<<384 + 6554, 256>>>(p_up1, Wu1, bu1, p_cv1raw, p_ps3, corr, p_srecip);
    phaseU3<<<1536 + 6554, 256>>>(p_cv1raw, p_ps3, p_up2, corr, p_srecip);
    phaseU4<<<1536 + 6553, 256>>>(p_up2, Wu2, bu2, p_cv2raw, p_ps4, corr, p_srecip);
    phaseU5<<<1536 + 6553, 256>>>(p_cv2raw, p_ps4, out, corr, p_srecip);
}